// round 1
// baseline (speedup 1.0000x reference)
#include <cuda_runtime.h>

// ---------------- problem constants ----------------
#define B_      16
#define C_      256
#define HEADS_  8
#define D_      32          // dim_head
#define HW_     4096        // 64*64
#define W_      64
#define LN_EPS  1e-5f

// ---------------- scratch (no allocations allowed) ----------------
__device__ float g_qkv[(size_t)B_ * 3 * C_ * HW_];   // 201 MB: q|k|v channel-major
__device__ float g_attn[(size_t)B_ * C_ * HW_];      // 67 MB
__device__ float g_ctx[B_ * HEADS_ * D_ * D_];       // 512 KB

// =====================================================================
// Kernel 1: qkv = w_qkv @ x   (per batch:  [768,256] x [256,4096])
// tiles: 64(M) x 64(N) x 16(K), 256 threads, 4x4 micro-tile
// =====================================================================
__global__ void __launch_bounds__(256) k_qkv_gemm(const float* __restrict__ x,
                                                  const float* __restrict__ w) {
    __shared__ float As[64][17];   // [m][k] padded
    __shared__ float Bs[16][64];   // [k][n]

    const int tid = threadIdx.x;
    const int m0  = blockIdx.y * 64;
    const size_t n0 = (size_t)blockIdx.x * 64;
    const int b  = (int)(n0 >> 12);     // 4096 pixels per batch, 64 | 4096
    const int p0 = (int)(n0 & 4095);

    const float* xb = x + (size_t)b * (C_ * HW_) + p0;
    float* ob = g_qkv + (size_t)b * (3 * C_ * HW_) + p0;

    const int tx = tid & 15, ty = tid >> 4;
    float acc[4][4] = {};

    for (int k0 = 0; k0 < C_; k0 += 16) {
#pragma unroll
        for (int i = 0; i < 4; i++) {               // A: 64x16
            int idx = tid + i * 256;
            int r = idx >> 4, c = idx & 15;
            As[r][c] = w[(size_t)(m0 + r) * C_ + (k0 + c)];
        }
#pragma unroll
        for (int i = 0; i < 4; i++) {               // B: 16x64 (coalesced)
            int idx = tid + i * 256;
            int r = idx >> 6, c = idx & 63;
            Bs[r][c] = xb[(size_t)(k0 + r) * HW_ + c];
        }
        __syncthreads();
#pragma unroll
        for (int kk = 0; kk < 16; kk++) {
            float a0 = As[ty * 4 + 0][kk];
            float a1 = As[ty * 4 + 1][kk];
            float a2 = As[ty * 4 + 2][kk];
            float a3 = As[ty * 4 + 3][kk];
            float4 bv = *(const float4*)&Bs[kk][tx * 4];
            acc[0][0] += a0 * bv.x; acc[0][1] += a0 * bv.y; acc[0][2] += a0 * bv.z; acc[0][3] += a0 * bv.w;
            acc[1][0] += a1 * bv.x; acc[1][1] += a1 * bv.y; acc[1][2] += a1 * bv.z; acc[1][3] += a1 * bv.w;
            acc[2][0] += a2 * bv.x; acc[2][1] += a2 * bv.y; acc[2][2] += a2 * bv.z; acc[2][3] += a2 * bv.w;
            acc[3][0] += a3 * bv.x; acc[3][1] += a3 * bv.y; acc[3][2] += a3 * bv.z; acc[3][3] += a3 * bv.w;
        }
        __syncthreads();
    }
#pragma unroll
    for (int i = 0; i < 4; i++) {
        float4 v = make_float4(acc[i][0], acc[i][1], acc[i][2], acc[i][3]);
        *(float4*)&ob[(size_t)(m0 + ty * 4 + i) * HW_ + tx * 4] = v;
    }
}

// =====================================================================
// Kernel 2: softmax over y (64 contiguous floats) for k channels, in place.
// rows: (b, kc in [0,256), x in [0,64))  -> 262144 rows; 1 warp / row.
// =====================================================================
__global__ void __launch_bounds__(256) k_softmax_k() {
    const int row  = blockIdx.x * 8 + (threadIdx.x >> 5);
    const int lane = threadIdx.x & 31;
    const int b   = row >> 14;          // 256*64 rows per batch
    const int rem = row & 16383;
    const int kc  = rem >> 6;
    const int xr  = rem & 63;

    float* ptr = g_qkv + (size_t)b * (3 * C_ * HW_) + (size_t)(C_ + kc) * HW_ + xr * W_;

    float v0 = ptr[lane], v1 = ptr[lane + 32];
    float m = fmaxf(v0, v1);
#pragma unroll
    for (int off = 16; off; off >>= 1)
        m = fmaxf(m, __shfl_xor_sync(0xffffffffu, m, off));
    float e0 = expf(v0 - m), e1 = expf(v1 - m);
    float s = e0 + e1;
#pragma unroll
    for (int off = 16; off; off >>= 1)
        s += __shfl_xor_sync(0xffffffffu, s, off);
    float inv = 1.0f / s;
    ptr[lane]      = e0 * inv;
    ptr[lane + 32] = e1 * inv;
}

// =====================================================================
// Kernel 3: context[b,h,d,e] = sum_p khat[b,h,d,p] * v[b,h,e,p]
// one block per (b,h); 256 threads; each thread a 2x2 (d,e) tile.
// =====================================================================
__global__ void __launch_bounds__(256) k_context() {
    const int bh = blockIdx.x;
    const int b = bh >> 3, h = bh & 7;
    __shared__ float ks[64][34];   // [pp][d] transposed, padded
    __shared__ float vs[64][34];   // [pp][e]

    const float* kb = g_qkv + (size_t)b * (3 * C_ * HW_) + (size_t)(C_     + h * D_) * HW_;
    const float* vb = g_qkv + (size_t)b * (3 * C_ * HW_) + (size_t)(2 * C_ + h * D_) * HW_;

    const int t = threadIdx.x;
    const int td = t >> 4, te = t & 15;
    float acc00 = 0.f, acc01 = 0.f, acc10 = 0.f, acc11 = 0.f;

    for (int pc = 0; pc < HW_; pc += 64) {
#pragma unroll
        for (int i = 0; i < 8; i++) {
            int idx = t + i * 256;
            int r = idx >> 6, c = idx & 63;   // r = d/e, c = pp  (coalesced gmem)
            ks[c][r] = kb[(size_t)r * HW_ + pc + c];
            vs[c][r] = vb[(size_t)r * HW_ + pc + c];
        }
        __syncthreads();
#pragma unroll 8
        for (int pp = 0; pp < 64; pp++) {
            float2 kv = *(const float2*)&ks[pp][td * 2];
            float2 vv = *(const float2*)&vs[pp][te * 2];
            acc00 += kv.x * vv.x; acc01 += kv.x * vv.y;
            acc10 += kv.y * vv.x; acc11 += kv.y * vv.y;
        }
        __syncthreads();
    }
    float* cb = g_ctx + (size_t)bh * (D_ * D_);
    cb[(td * 2 + 0) * D_ + te * 2 + 0] = acc00;
    cb[(td * 2 + 0) * D_ + te * 2 + 1] = acc01;
    cb[(td * 2 + 1) * D_ + te * 2 + 0] = acc10;
    cb[(td * 2 + 1) * D_ + te * 2 + 1] = acc11;
}

// =====================================================================
// Kernel 4: softmax(q over d) then attn[b, h*32+d, p] = sum_e ctx[d,e]*qhat[e,p]
// block = (b, h, tile of 128 pixels); 256 threads.
// =====================================================================
__global__ void __launch_bounds__(256) k_apply() {
    const int pt = blockIdx.x;     // 0..31 (128 pixels each)
    const int h  = blockIdx.y;
    const int b  = blockIdx.z;
    const int bh = b * HEADS_ + h;

    __shared__ float qs[32][129];  // [d][pixel], padded
    __shared__ float cs[32][32];   // ctx[d][e]

    const int tid = threadIdx.x;
    const float* qb = g_qkv + (size_t)b * (3 * C_ * HW_) + (size_t)(h * D_) * HW_ + pt * 128;

#pragma unroll
    for (int i = 0; i < 16; i++) {
        int idx = tid + i * 256;
        int r = idx >> 7, c = idx & 127;
        qs[r][c] = qb[(size_t)r * HW_ + c];
    }
#pragma unroll
    for (int i = 0; i < 4; i++) {
        int idx = tid + i * 256;
        cs[idx >> 5][idx & 31] = g_ctx[(size_t)bh * (D_ * D_) + idx];
    }
    __syncthreads();

    if (tid < 128) {                       // per-pixel softmax over d=32
        float m = -1e30f;
#pragma unroll
        for (int dd = 0; dd < 32; dd++) m = fmaxf(m, qs[dd][tid]);
        float s = 0.f;
#pragma unroll
        for (int dd = 0; dd < 32; dd++) {
            float e = expf(qs[dd][tid] - m);
            s += e;
            qs[dd][tid] = e;
        }
        float inv = 1.0f / s;
#pragma unroll
        for (int dd = 0; dd < 32; dd++) qs[dd][tid] *= inv;
    }
    __syncthreads();

    const int p  = tid & 127;
    const int d0 = (tid >> 7) * 16;
    float acc[16] = {};
#pragma unroll
    for (int e = 0; e < 32; e++) {
        float qv = qs[e][p];
#pragma unroll
        for (int i = 0; i < 16; i++) acc[i] += cs[d0 + i][e] * qv;
    }
    float* ab = g_attn + (size_t)b * (C_ * HW_) + (size_t)(h * D_ + d0) * HW_ + pt * 128 + p;
#pragma unroll
    for (int i = 0; i < 16; i++) ab[(size_t)i * HW_] = acc[i];
}

// =====================================================================
// Kernel 5: y = w_out @ attn + b_out, then LayerNorm over channels.
// block = 32 pixels x 256 channels; thread t owns output channel o=t.
// =====================================================================
__global__ void __launch_bounds__(256) k_out_ln(const float* __restrict__ w_out,
                                                const float* __restrict__ b_out,
                                                const float* __restrict__ gamma,
                                                const float* __restrict__ beta,
                                                float* __restrict__ out) {
    const int blk = blockIdx.x;
    const int b   = blk >> 7;        // 128 pixel-tiles per batch
    const int p0  = (blk & 127) * 32;

    __shared__ float As[32][36];          // [c][pixel] chunk, float4-aligned rows
    __shared__ float ybuf[256][33];       // [o][pixel]
    __shared__ float red1[8][32], red2[8][32];
    __shared__ float mu_s[32], rs_s[32];

    const int t = threadIdx.x;            // output channel
    const float* ab = g_attn + (size_t)b * (C_ * HW_) + p0;

    float acc[32] = {};
    for (int kc = 0; kc < 8; kc++) {
        __syncthreads();
#pragma unroll
        for (int i = 0; i < 4; i++) {
            int idx = t + i * 256;
            int r = idx >> 5, c = idx & 31;
            As[r][c] = ab[(size_t)(kc * 32 + r) * HW_ + c];
        }
        __syncthreads();

        const float4* w4 = (const float4*)(w_out + (size_t)t * C_ + kc * 32);
#pragma unroll
        for (int cc4 = 0; cc4 < 8; cc4++) {
            float4 wv = w4[cc4];
            const float* wp = &wv.x;
#pragma unroll
            for (int j = 0; j < 4; j++) {
                float wj = wp[j];
                const float4* Ar = (const float4*)&As[cc4 * 4 + j][0];
#pragma unroll
                for (int p4 = 0; p4 < 8; p4++) {
                    float4 av = Ar[p4];
                    acc[p4 * 4 + 0] += wj * av.x;
                    acc[p4 * 4 + 1] += wj * av.y;
                    acc[p4 * 4 + 2] += wj * av.z;
                    acc[p4 * 4 + 3] += wj * av.w;
                }
            }
        }
    }

    float bias = b_out[t];
#pragma unroll
    for (int p = 0; p < 32; p++) ybuf[t][p] = acc[p] + bias;
    __syncthreads();

    // per-pixel mean/var over 256 channels
    {
        const int p = t & 31, g = t >> 5;
        float s1 = 0.f, s2 = 0.f;
#pragma unroll
        for (int i = 0; i < 32; i++) {
            float v = ybuf[g * 32 + i][p];
            s1 += v; s2 += v * v;
        }
        red1[g][p] = s1; red2[g][p] = s2;
    }
    __syncthreads();
    if (t < 32) {
        float m1 = 0.f, m2 = 0.f;
#pragma unroll
        for (int g = 0; g < 8; g++) { m1 += red1[g][t]; m2 += red2[g][t]; }
        float mu  = m1 * (1.0f / 256.0f);
        float var = m2 * (1.0f / 256.0f) - mu * mu;
        mu_s[t] = mu;
        rs_s[t] = rsqrtf(var + LN_EPS);
    }
    __syncthreads();

    // coalesced writeback: warp lanes sweep pixels
    {
        const int p = t & 31, g = t >> 5;
        float* ob = out + (size_t)b * (C_ * HW_) + p0;
        float mu = mu_s[p], rs = rs_s[p];
#pragma unroll
        for (int i = 0; i < 32; i++) {
            int o = g * 32 + i;
            float v = (ybuf[o][p] - mu) * rs * gamma[o] + beta[o];
            ob[(size_t)o * HW_ + p] = v;
        }
    }
}

// =====================================================================
extern "C" void kernel_launch(void* const* d_in, const int* in_sizes, int n_in,
                              void* d_out, int out_size) {
    const float* x      = (const float*)d_in[0];
    const float* w_qkv  = (const float*)d_in[1];
    const float* w_out  = (const float*)d_in[2];
    const float* b_out  = (const float*)d_in[3];
    const float* gamma  = (const float*)d_in[4];
    const float* beta   = (const float*)d_in[5];
    float* out = (float*)d_out;

    dim3 g1((B_ * HW_) / 64, (3 * C_) / 64);      // 1024 x 12
    k_qkv_gemm<<<g1, 256>>>(x, w_qkv);

    k_softmax_k<<<(B_ * C_ * W_) / 8, 256>>>();   // 32768 blocks

    k_context<<<B_ * HEADS_, 256>>>();            // 128 blocks

    dim3 g4(HW_ / 128, HEADS_, B_);               // 32 x 8 x 16
    k_apply<<<g4, 256>>>();

    k_out_ln<<<(B_ * HW_) / 32, 256>>>(w_out, b_out, gamma, beta, out);
}

// round 2
// speedup vs baseline: 2.0125x; 2.0125x over previous
#include <cuda_runtime.h>

// ---------------- problem constants ----------------
#define B_      16
#define C_      256
#define HEADS_  8
#define D_      32          // dim_head
#define HW_     4096        // 64*64
#define W_      64
#define LN_EPS  1e-5f

// ---------------- scratch (no allocations allowed) ----------------
__device__ float g_qkv[(size_t)B_ * 3 * C_ * HW_];   // 201 MB: q|k|v channel-major
__device__ float g_attn[(size_t)B_ * C_ * HW_];      // 67 MB
__device__ float g_ctx[B_ * HEADS_ * D_ * D_];       // 512 KB

// ---------------- tf32 helpers ----------------
__device__ __forceinline__ unsigned f2tf32(float f) {
    unsigned u;
    asm("cvt.rna.tf32.f32 %0, %1;" : "=r"(u) : "f"(f));
    return u;
}

__device__ __forceinline__ void mma_tf32(float* c, const unsigned* a, const unsigned* b) {
    asm volatile(
        "mma.sync.aligned.m16n8k8.row.col.f32.tf32.tf32.f32 "
        "{%0,%1,%2,%3}, {%4,%5,%6,%7}, {%8,%9}, {%0,%1,%2,%3};"
        : "+f"(c[0]), "+f"(c[1]), "+f"(c[2]), "+f"(c[3])
        : "r"(a[0]), "r"(a[1]), "r"(a[2]), "r"(a[3]), "r"(b[0]), "r"(b[1]));
}

// =====================================================================
// Kernel 1: qkv = w_qkv @ x   (per batch: [768,256] x [256,4096]) — tf32 MMA
// block tile 128(M) x 128(N) x 32(K); 8 warps (2x4); warp tile 64x32.
// =====================================================================
__global__ void __launch_bounds__(256) k_qkv_gemm_tf32(const float* __restrict__ x,
                                                       const float* __restrict__ w) {
    __shared__ unsigned As[128][36];    // pad 36: frag banks (4g+tg) conflict-free
    __shared__ unsigned Bs[32][136];    // pad 136: frag banks (8tg+g) conflict-free

    const int tid  = threadIdx.x;
    const int warp = tid >> 5, lane = tid & 31;
    const int g = lane >> 2, tg = lane & 3;
    const int wm = warp >> 2, wn = warp & 3;      // 2 x 4 warp grid

    const int m0 = blockIdx.y * 128;
    const size_t n0 = (size_t)blockIdx.x * 128;
    const int b  = (int)(n0 >> 12);               // 128 | 4096
    const int p0 = (int)(n0 & 4095);

    const float* xb = x + (size_t)b * (C_ * HW_) + p0;
    float* ob = g_qkv + (size_t)b * (3 * C_ * HW_) + p0;

    float acc[4][4][4] = {};

    for (int k0 = 0; k0 < C_; k0 += 32) {
#pragma unroll
        for (int i = 0; i < 16; i++) {            // A: 128x32 (coalesced rows)
            int idx = tid + i * 256;
            int r = idx >> 5, c = idx & 31;
            As[r][c] = f2tf32(w[(size_t)(m0 + r) * C_ + k0 + c]);
        }
#pragma unroll
        for (int i = 0; i < 16; i++) {            // B: 32x128 (coalesced)
            int idx = tid + i * 256;
            int r = idx >> 7, c = idx & 127;
            Bs[r][c] = f2tf32(xb[(size_t)(k0 + r) * HW_ + c]);
        }
        __syncthreads();

#pragma unroll
        for (int ks = 0; ks < 4; ks++) {
            const int kb = ks * 8;
            unsigned af[4][4], bf[4][2];
#pragma unroll
            for (int mt = 0; mt < 4; mt++) {
                int rm = wm * 64 + mt * 16;
                af[mt][0] = As[rm + g][kb + tg];
                af[mt][1] = As[rm + g + 8][kb + tg];
                af[mt][2] = As[rm + g][kb + tg + 4];
                af[mt][3] = As[rm + g + 8][kb + tg + 4];
            }
#pragma unroll
            for (int nt = 0; nt < 4; nt++) {
                int cn = wn * 32 + nt * 8 + g;
                bf[nt][0] = Bs[kb + tg][cn];
                bf[nt][1] = Bs[kb + tg + 4][cn];
            }
#pragma unroll
            for (int mt = 0; mt < 4; mt++)
#pragma unroll
                for (int nt = 0; nt < 4; nt++)
                    mma_tf32(acc[mt][nt], af[mt], bf[nt]);
        }
        __syncthreads();
    }

#pragma unroll
    for (int mt = 0; mt < 4; mt++) {
        int r0 = m0 + wm * 64 + mt * 16 + g;
#pragma unroll
        for (int nt = 0; nt < 4; nt++) {
            int c = wn * 32 + nt * 8 + tg * 2;
            *(float2*)&ob[(size_t)r0 * HW_ + c]       = make_float2(acc[mt][nt][0], acc[mt][nt][1]);
            *(float2*)&ob[(size_t)(r0 + 8) * HW_ + c] = make_float2(acc[mt][nt][2], acc[mt][nt][3]);
        }
    }
}

// =====================================================================
// Kernel 2: softmax over y (64 contiguous floats) for k channels, in place.
// =====================================================================
__global__ void __launch_bounds__(256) k_softmax_k() {
    const int row  = blockIdx.x * 8 + (threadIdx.x >> 5);
    const int lane = threadIdx.x & 31;
    const int b   = row >> 14;
    const int rem = row & 16383;
    const int kc  = rem >> 6;
    const int xr  = rem & 63;

    float* ptr = g_qkv + (size_t)b * (3 * C_ * HW_) + (size_t)(C_ + kc) * HW_ + xr * W_;

    float v0 = ptr[lane], v1 = ptr[lane + 32];
    float m = fmaxf(v0, v1);
#pragma unroll
    for (int off = 16; off; off >>= 1)
        m = fmaxf(m, __shfl_xor_sync(0xffffffffu, m, off));
    float e0 = expf(v0 - m), e1 = expf(v1 - m);
    float s = e0 + e1;
#pragma unroll
    for (int off = 16; off; off >>= 1)
        s += __shfl_xor_sync(0xffffffffu, s, off);
    float inv = 1.0f / s;
    ptr[lane]      = e0 * inv;
    ptr[lane + 32] = e1 * inv;
}

// =====================================================================
// Kernel 3: context[b,h,d,e] = sum_p khat[b,h,d,p] * v[b,h,e,p]  (fp32)
// =====================================================================
__global__ void __launch_bounds__(256) k_context() {
    const int bh = blockIdx.x;
    const int b = bh >> 3, h = bh & 7;
    __shared__ float ks[64][34];
    __shared__ float vs[64][34];

    const float* kb = g_qkv + (size_t)b * (3 * C_ * HW_) + (size_t)(C_     + h * D_) * HW_;
    const float* vb = g_qkv + (size_t)b * (3 * C_ * HW_) + (size_t)(2 * C_ + h * D_) * HW_;

    const int t = threadIdx.x;
    const int td = t >> 4, te = t & 15;
    float acc00 = 0.f, acc01 = 0.f, acc10 = 0.f, acc11 = 0.f;

    for (int pc = 0; pc < HW_; pc += 64) {
#pragma unroll
        for (int i = 0; i < 8; i++) {
            int idx = t + i * 256;
            int r = idx >> 6, c = idx & 63;
            ks[c][r] = kb[(size_t)r * HW_ + pc + c];
            vs[c][r] = vb[(size_t)r * HW_ + pc + c];
        }
        __syncthreads();
#pragma unroll 8
        for (int pp = 0; pp < 64; pp++) {
            float2 kv = *(const float2*)&ks[pp][td * 2];
            float2 vv = *(const float2*)&vs[pp][te * 2];
            acc00 += kv.x * vv.x; acc01 += kv.x * vv.y;
            acc10 += kv.y * vv.x; acc11 += kv.y * vv.y;
        }
        __syncthreads();
    }
    float* cb = g_ctx + (size_t)bh * (D_ * D_);
    cb[(td * 2 + 0) * D_ + te * 2 + 0] = acc00;
    cb[(td * 2 + 0) * D_ + te * 2 + 1] = acc01;
    cb[(td * 2 + 1) * D_ + te * 2 + 0] = acc10;
    cb[(td * 2 + 1) * D_ + te * 2 + 1] = acc11;
}

// =====================================================================
// Kernel 4: softmax(q over d) then attn = ctx @ qhat  (fp32)
// =====================================================================
__global__ void __launch_bounds__(256) k_apply() {
    const int pt = blockIdx.x;
    const int h  = blockIdx.y;
    const int b  = blockIdx.z;
    const int bh = b * HEADS_ + h;

    __shared__ float qs[32][129];
    __shared__ float cs[32][32];

    const int tid = threadIdx.x;
    const float* qb = g_qkv + (size_t)b * (3 * C_ * HW_) + (size_t)(h * D_) * HW_ + pt * 128;

#pragma unroll
    for (int i = 0; i < 16; i++) {
        int idx = tid + i * 256;
        int r = idx >> 7, c = idx & 127;
        qs[r][c] = qb[(size_t)r * HW_ + c];
    }
#pragma unroll
    for (int i = 0; i < 4; i++) {
        int idx = tid + i * 256;
        cs[idx >> 5][idx & 31] = g_ctx[(size_t)bh * (D_ * D_) + idx];
    }
    __syncthreads();

    if (tid < 128) {
        float m = -1e30f;
#pragma unroll
        for (int dd = 0; dd < 32; dd++) m = fmaxf(m, qs[dd][tid]);
        float s = 0.f;
#pragma unroll
        for (int dd = 0; dd < 32; dd++) {
            float e = expf(qs[dd][tid] - m);
            s += e;
            qs[dd][tid] = e;
        }
        float inv = 1.0f / s;
#pragma unroll
        for (int dd = 0; dd < 32; dd++) qs[dd][tid] *= inv;
    }
    __syncthreads();

    const int p  = tid & 127;
    const int d0 = (tid >> 7) * 16;
    float acc[16] = {};
#pragma unroll
    for (int e = 0; e < 32; e++) {
        float qv = qs[e][p];
#pragma unroll
        for (int i = 0; i < 16; i++) acc[i] += cs[d0 + i][e] * qv;
    }
    float* ab = g_attn + (size_t)b * (C_ * HW_) + (size_t)(h * D_ + d0) * HW_ + pt * 128 + p;
#pragma unroll
    for (int i = 0; i < 16; i++) ab[(size_t)i * HW_] = acc[i];
}

// =====================================================================
// Kernel 5: y = w_out @ attn + b_out, fused channel-LayerNorm — tf32 MMA
// block tile 256(M = all channels) x 64(N pixels) x 32(K); 8 warps (4x2).
// LN stats from register fragments via shfl + smem atomics (no ybuf).
// =====================================================================
__global__ void __launch_bounds__(256) k_out_ln_tf32(const float* __restrict__ w_out,
                                                     const float* __restrict__ b_out,
                                                     const float* __restrict__ gamma,
                                                     const float* __restrict__ beta,
                                                     float* __restrict__ out) {
    __shared__ unsigned As[256][36];
    __shared__ unsigned Bs[32][72];
    __shared__ float s_sum[64], s_sq[64], s_mu[64], s_rs[64];

    const int tid  = threadIdx.x;
    const int warp = tid >> 5, lane = tid & 31;
    const int g = lane >> 2, tg = lane & 3;
    const int wm = warp >> 1, wn = warp & 1;      // 4 x 2 warp grid

    const int blk = blockIdx.x;
    const int b   = blk >> 6;                     // 64 pixel-tiles per batch
    const int p0  = (blk & 63) * 64;

    const float* ab = g_attn + (size_t)b * (C_ * HW_) + p0;

    if (tid < 64) { s_sum[tid] = 0.f; s_sq[tid] = 0.f; }

    float acc[4][4][4] = {};

    for (int k0 = 0; k0 < C_; k0 += 32) {
#pragma unroll
        for (int i = 0; i < 32; i++) {            // A: 256x32 of w_out
            int idx = tid + i * 256;
            int r = idx >> 5, c = idx & 31;
            As[r][c] = f2tf32(w_out[(size_t)r * C_ + k0 + c]);
        }
#pragma unroll
        for (int i = 0; i < 8; i++) {             // B: 32x64 of attn
            int idx = tid + i * 256;
            int r = idx >> 6, c = idx & 63;
            Bs[r][c] = f2tf32(ab[(size_t)(k0 + r) * HW_ + c]);
        }
        __syncthreads();

#pragma unroll
        for (int ks = 0; ks < 4; ks++) {
            const int kb = ks * 8;
            unsigned af[4][4], bf[4][2];
#pragma unroll
            for (int mt = 0; mt < 4; mt++) {
                int rm = wm * 64 + mt * 16;
                af[mt][0] = As[rm + g][kb + tg];
                af[mt][1] = As[rm + g + 8][kb + tg];
                af[mt][2] = As[rm + g][kb + tg + 4];
                af[mt][3] = As[rm + g + 8][kb + tg + 4];
            }
#pragma unroll
            for (int nt = 0; nt < 4; nt++) {
                int cn = wn * 32 + nt * 8 + g;
                bf[nt][0] = Bs[kb + tg][cn];
                bf[nt][1] = Bs[kb + tg + 4][cn];
            }
#pragma unroll
            for (int mt = 0; mt < 4; mt++)
#pragma unroll
                for (int nt = 0; nt < 4; nt++)
                    mma_tf32(acc[mt][nt], af[mt], bf[nt]);
        }
        __syncthreads();
    }

    // bias / gamma / beta for this thread's 8 rows
    float bias0[4], bias1[4], gam0[4], gam1[4], bet0[4], bet1[4];
#pragma unroll
    for (int mt = 0; mt < 4; mt++) {
        int r = wm * 64 + mt * 16 + g;
        bias0[mt] = b_out[r]; bias1[mt] = b_out[r + 8];
        gam0[mt]  = gamma[r]; gam1[mt]  = gamma[r + 8];
        bet0[mt]  = beta[r];  bet1[mt]  = beta[r + 8];
    }
#pragma unroll
    for (int mt = 0; mt < 4; mt++)
#pragma unroll
        for (int nt = 0; nt < 4; nt++) {
            acc[mt][nt][0] += bias0[mt]; acc[mt][nt][1] += bias0[mt];
            acc[mt][nt][2] += bias1[mt]; acc[mt][nt][3] += bias1[mt];
        }

    // per-column (pixel) partial sums over this warp's 64 rows
#pragma unroll
    for (int nt = 0; nt < 4; nt++) {
        float s0 = 0.f, s1 = 0.f, q0 = 0.f, q1 = 0.f;
#pragma unroll
        for (int mt = 0; mt < 4; mt++) {
            float v0 = acc[mt][nt][0], v1 = acc[mt][nt][1];
            float v2 = acc[mt][nt][2], v3 = acc[mt][nt][3];
            s0 += v0 + v2; s1 += v1 + v3;
            q0 += v0 * v0 + v2 * v2; q1 += v1 * v1 + v3 * v3;
        }
#pragma unroll
        for (int off = 4; off < 32; off <<= 1) {   // reduce across g
            s0 += __shfl_xor_sync(0xffffffffu, s0, off);
            s1 += __shfl_xor_sync(0xffffffffu, s1, off);
            q0 += __shfl_xor_sync(0xffffffffu, q0, off);
            q1 += __shfl_xor_sync(0xffffffffu, q1, off);
        }
        if (g == 0) {
            int c = wn * 32 + nt * 8 + tg * 2;
            atomicAdd(&s_sum[c], s0);     atomicAdd(&s_sq[c], q0);
            atomicAdd(&s_sum[c + 1], s1); atomicAdd(&s_sq[c + 1], q1);
        }
    }
    __syncthreads();

    if (tid < 64) {
        float mu  = s_sum[tid] * (1.0f / 256.0f);
        float var = s_sq[tid] * (1.0f / 256.0f) - mu * mu;
        s_mu[tid] = mu;
        s_rs[tid] = rsqrtf(var + LN_EPS);
    }
    __syncthreads();

    float* ob = out + (size_t)b * (C_ * HW_) + p0;
#pragma unroll
    for (int mt = 0; mt < 4; mt++) {
        int r = wm * 64 + mt * 16 + g;
#pragma unroll
        for (int nt = 0; nt < 4; nt++) {
            int c = wn * 32 + nt * 8 + tg * 2;
            float mu0 = s_mu[c], rs0 = s_rs[c];
            float mu1 = s_mu[c + 1], rs1 = s_rs[c + 1];
            float o0 = (acc[mt][nt][0] - mu0) * rs0 * gam0[mt] + bet0[mt];
            float o1 = (acc[mt][nt][1] - mu1) * rs1 * gam0[mt] + bet0[mt];
            float o2 = (acc[mt][nt][2] - mu0) * rs0 * gam1[mt] + bet1[mt];
            float o3 = (acc[mt][nt][3] - mu1) * rs1 * gam1[mt] + bet1[mt];
            *(float2*)&ob[(size_t)r * HW_ + c]       = make_float2(o0, o1);
            *(float2*)&ob[(size_t)(r + 8) * HW_ + c] = make_float2(o2, o3);
        }
    }
}

// =====================================================================
extern "C" void kernel_launch(void* const* d_in, const int* in_sizes, int n_in,
                              void* d_out, int out_size) {
    const float* x      = (const float*)d_in[0];
    const float* w_qkv  = (const float*)d_in[1];
    const float* w_out  = (const float*)d_in[2];
    const float* b_out  = (const float*)d_in[3];
    const float* gamma  = (const float*)d_in[4];
    const float* beta   = (const float*)d_in[5];
    float* out = (float*)d_out;

    dim3 g1((B_ * HW_) / 128, (3 * C_) / 128);    // 512 x 6
    k_qkv_gemm_tf32<<<g1, 256>>>(x, w_qkv);

    k_softmax_k<<<(B_ * C_ * W_) / 8, 256>>>();   // 32768 blocks

    k_context<<<B_ * HEADS_, 256>>>();            // 128 blocks

    dim3 g4(HW_ / 128, HEADS_, B_);               // 32 x 8 x 16
    k_apply<<<g4, 256>>>();

    k_out_ln_tf32<<<(B_ * HW_) / 64, 256>>>(w_out, b_out, gamma, beta, out);
}

// round 3
// speedup vs baseline: 2.4920x; 1.2383x over previous
#include <cuda_runtime.h>

// ---------------- problem constants ----------------
#define B_      16
#define C_      256
#define HEADS_  8
#define D_      32          // dim_head
#define HW_     4096        // 64*64
#define W_      64
#define LN_EPS  1e-5f

// ---------------- scratch (no allocations allowed) ----------------
__device__ float g_qkv[(size_t)B_ * 3 * C_ * HW_];    // qhat | khat | v, channel-major
__device__ float g_ctxp[128 * 32 * (D_ * D_)];        // 16MB context partials
__device__ float g_weff[(size_t)B_ * C_ * C_];        // 4MB  w_eff per batch

// ---------------- tf32 helpers ----------------
__device__ __forceinline__ unsigned f2tf32(float f) {
    unsigned u;
    asm("cvt.rna.tf32.f32 %0, %1;" : "=r"(u) : "f"(f));
    return u;
}

__device__ __forceinline__ void mma_tf32(float* c, const unsigned* a, const unsigned* b) {
    asm volatile(
        "mma.sync.aligned.m16n8k8.row.col.f32.tf32.tf32.f32 "
        "{%0,%1,%2,%3}, {%4,%5,%6,%7}, {%8,%9}, {%0,%1,%2,%3};"
        : "+f"(c[0]), "+f"(c[1]), "+f"(c[2]), "+f"(c[3])
        : "r"(a[0]), "r"(a[1]), "r"(a[2]), "r"(a[3]), "r"(b[0]), "r"(b[1]));
}

// =====================================================================
// Kernel 1: qkv = w_qkv @ x  (tf32 MMA, 128x128x32 tiles, 8 warps 2x4)
// Fused epilogues:
//   blockIdx.y 0,1 -> q rows: softmax over d=32 (intra-warp, per pixel col)
//   blockIdx.y 2,3 -> k rows: softmax over y=64 (2-warp pair via smem)
//   blockIdx.y 4,5 -> v rows: plain store
// =====================================================================
__global__ void __launch_bounds__(256) k_qkv_gemm_tf32(const float* __restrict__ x,
                                                       const float* __restrict__ w) {
    __shared__ unsigned As[128][36];
    __shared__ unsigned Bs[32][136];
    __shared__ float red[2][4][128];   // [phase][wn][block row] partials for k-softmax

    const int tid  = threadIdx.x;
    const int warp = tid >> 5, lane = tid & 31;
    const int g = lane >> 2, tg = lane & 3;
    const int wm = warp >> 2, wn = warp & 3;      // 2 x 4 warp grid

    const int m0 = blockIdx.y * 128;
    const size_t n0 = (size_t)blockIdx.x * 128;
    const int b  = (int)(n0 >> 12);
    const int p0 = (int)(n0 & 4095);

    const float* xb = x + (size_t)b * (C_ * HW_) + p0;
    float* ob = g_qkv + (size_t)b * (3 * C_ * HW_) + p0;

    float acc[4][4][4] = {};

    for (int k0 = 0; k0 < C_; k0 += 32) {
#pragma unroll
        for (int i = 0; i < 16; i++) {
            int idx = tid + i * 256;
            int r = idx >> 5, c = idx & 31;
            As[r][c] = f2tf32(w[(size_t)(m0 + r) * C_ + k0 + c]);
        }
#pragma unroll
        for (int i = 0; i < 16; i++) {
            int idx = tid + i * 256;
            int r = idx >> 7, c = idx & 127;
            Bs[r][c] = f2tf32(xb[(size_t)(k0 + r) * HW_ + c]);
        }
        __syncthreads();

#pragma unroll
        for (int ks = 0; ks < 4; ks++) {
            const int kb = ks * 8;
            unsigned af[4][4], bf[4][2];
#pragma unroll
            for (int mt = 0; mt < 4; mt++) {
                int rm = wm * 64 + mt * 16;
                af[mt][0] = As[rm + g][kb + tg];
                af[mt][1] = As[rm + g + 8][kb + tg];
                af[mt][2] = As[rm + g][kb + tg + 4];
                af[mt][3] = As[rm + g + 8][kb + tg + 4];
            }
#pragma unroll
            for (int nt = 0; nt < 4; nt++) {
                int cn = wn * 32 + nt * 8 + g;
                bf[nt][0] = Bs[kb + tg][cn];
                bf[nt][1] = Bs[kb + tg + 4][cn];
            }
#pragma unroll
            for (int mt = 0; mt < 4; mt++)
#pragma unroll
                for (int nt = 0; nt < 4; nt++)
                    mma_tf32(acc[mt][nt], af[mt], bf[nt]);
        }
        __syncthreads();
    }

    const int sect = blockIdx.y >> 1;   // 0=q, 1=k, 2=v

    if (sect == 0) {
        // ---- q softmax over d: head = mt-pair; rows live across g (lane bits 2..4)
#pragma unroll
        for (int p = 0; p < 2; p++) {
#pragma unroll
            for (int nt = 0; nt < 4; nt++) {
#pragma unroll
                for (int j = 0; j < 2; j++) {
                    float v0 = acc[2 * p][nt][j],     v1 = acc[2 * p][nt][j + 2];
                    float v2 = acc[2 * p + 1][nt][j], v3 = acc[2 * p + 1][nt][j + 2];
                    float m = fmaxf(fmaxf(v0, v1), fmaxf(v2, v3));
                    m = fmaxf(m, __shfl_xor_sync(0xffffffffu, m, 4));
                    m = fmaxf(m, __shfl_xor_sync(0xffffffffu, m, 8));
                    m = fmaxf(m, __shfl_xor_sync(0xffffffffu, m, 16));
                    float e0 = __expf(v0 - m), e1 = __expf(v1 - m);
                    float e2 = __expf(v2 - m), e3 = __expf(v3 - m);
                    float s = e0 + e1 + e2 + e3;
                    s += __shfl_xor_sync(0xffffffffu, s, 4);
                    s += __shfl_xor_sync(0xffffffffu, s, 8);
                    s += __shfl_xor_sync(0xffffffffu, s, 16);
                    float inv = 1.0f / s;
                    acc[2 * p][nt][j]         = e0 * inv;
                    acc[2 * p][nt][j + 2]     = e1 * inv;
                    acc[2 * p + 1][nt][j]     = e2 * inv;
                    acc[2 * p + 1][nt][j + 2] = e3 * inv;
                }
            }
        }
    } else if (sect == 1) {
        // ---- k softmax over y=64: warp owns 32 cols; partner warp = wn^1
        float mloc[4][2], sloc[4][2];
#pragma unroll
        for (int mt = 0; mt < 4; mt++)
#pragma unroll
            for (int hf = 0; hf < 2; hf++) {
                float m = -1e30f;
#pragma unroll
                for (int nt = 0; nt < 4; nt++) {
                    m = fmaxf(m, acc[mt][nt][hf * 2]);
                    m = fmaxf(m, acc[mt][nt][hf * 2 + 1]);
                }
                m = fmaxf(m, __shfl_xor_sync(0xffffffffu, m, 1));
                m = fmaxf(m, __shfl_xor_sync(0xffffffffu, m, 2));
                mloc[mt][hf] = m;
                if (tg == 0) red[0][wn][wm * 64 + mt * 16 + hf * 8 + g] = m;
            }
        __syncthreads();
#pragma unroll
        for (int mt = 0; mt < 4; mt++)
#pragma unroll
            for (int hf = 0; hf < 2; hf++) {
                int ri = wm * 64 + mt * 16 + hf * 8 + g;
                float m = fmaxf(mloc[mt][hf], red[0][wn ^ 1][ri]);
                float s = 0.f;
#pragma unroll
                for (int nt = 0; nt < 4; nt++) {
                    float e0 = __expf(acc[mt][nt][hf * 2] - m);
                    float e1 = __expf(acc[mt][nt][hf * 2 + 1] - m);
                    acc[mt][nt][hf * 2]     = e0;
                    acc[mt][nt][hf * 2 + 1] = e1;
                    s += e0 + e1;
                }
                s += __shfl_xor_sync(0xffffffffu, s, 1);
                s += __shfl_xor_sync(0xffffffffu, s, 2);
                sloc[mt][hf] = s;
                if (tg == 0) red[1][wn][ri] = s;
            }
        __syncthreads();
#pragma unroll
        for (int mt = 0; mt < 4; mt++)
#pragma unroll
            for (int hf = 0; hf < 2; hf++) {
                int ri = wm * 64 + mt * 16 + hf * 8 + g;
                float inv = 1.0f / (sloc[mt][hf] + red[1][wn ^ 1][ri]);
#pragma unroll
                for (int nt = 0; nt < 4; nt++) {
                    acc[mt][nt][hf * 2]     *= inv;
                    acc[mt][nt][hf * 2 + 1] *= inv;
                }
            }
    }

#pragma unroll
    for (int mt = 0; mt < 4; mt++) {
        int r0 = m0 + wm * 64 + mt * 16 + g;
#pragma unroll
        for (int nt = 0; nt < 4; nt++) {
            int c = wn * 32 + nt * 8 + tg * 2;
            *(float2*)&ob[(size_t)r0 * HW_ + c]       = make_float2(acc[mt][nt][0], acc[mt][nt][1]);
            *(float2*)&ob[(size_t)(r0 + 8) * HW_ + c] = make_float2(acc[mt][nt][2], acc[mt][nt][3]);
        }
    }
}

// =====================================================================
// Kernel 2: context partials. grid (8 splits, 128 bh); block 256 =
// 4 pp-groups x (8x8 threads, 4x4 micro-tile). 512 pixels per block.
// =====================================================================
__global__ void __launch_bounds__(256) k_context() {
    const int s  = blockIdx.x;
    const int bh = blockIdx.y;
    const int b = bh >> 3, h = bh & 7;

    __shared__ float ks[128][36];
    __shared__ float vs[128][36];

    const float* kb = g_qkv + (size_t)b * (3 * C_ * HW_) + (size_t)(C_     + h * D_) * HW_;
    const float* vb = g_qkv + (size_t)b * (3 * C_ * HW_) + (size_t)(2 * C_ + h * D_) * HW_;

    const int t = threadIdx.x;
    const int ppg = t >> 6;
    const int t64 = t & 63;
    const int td = t64 >> 3, te = t64 & 7;

    float acc[4][4] = {};

    for (int chunk = 0; chunk < 4; chunk++) {
        const int pc = s * 512 + chunk * 128;
#pragma unroll
        for (int i = 0; i < 4; i++) {
            int idx = t + i * 256;
            int r = idx >> 5, c4 = idx & 31;
            float4 kv = *(const float4*)&kb[(size_t)r * HW_ + pc + c4 * 4];
            float4 vv = *(const float4*)&vb[(size_t)r * HW_ + pc + c4 * 4];
            ks[c4 * 4 + 0][r] = kv.x; ks[c4 * 4 + 1][r] = kv.y;
            ks[c4 * 4 + 2][r] = kv.z; ks[c4 * 4 + 3][r] = kv.w;
            vs[c4 * 4 + 0][r] = vv.x; vs[c4 * 4 + 1][r] = vv.y;
            vs[c4 * 4 + 2][r] = vv.z; vs[c4 * 4 + 3][r] = vv.w;
        }
        __syncthreads();
#pragma unroll 4
        for (int pp = ppg; pp < 128; pp += 4) {
            float4 ka = *(const float4*)&ks[pp][td * 4];
            float4 va = *(const float4*)&vs[pp][te * 4];
            const float* kp = &ka.x;
            const float* vp = &va.x;
#pragma unroll
            for (int i = 0; i < 4; i++)
#pragma unroll
                for (int j = 0; j < 4; j++)
                    acc[i][j] += kp[i] * vp[j];
        }
        __syncthreads();
    }

    float* op = g_ctxp + ((size_t)bh * 32 + s * 4 + ppg) * (D_ * D_);
#pragma unroll
    for (int i = 0; i < 4; i++)
        *(float4*)&op[(td * 4 + i) * D_ + te * 4] =
            make_float4(acc[i][0], acc[i][1], acc[i][2], acc[i][3]);
}

// =====================================================================
// Kernel 3: reduce ctx partials + w_eff[b][o][h*32+e] = sum_d w_out[o][h*32+d]*ctx[d][e]
// grid (8 heads, 16 batches); block 256 (thread = output channel o).
// =====================================================================
__global__ void __launch_bounds__(256) k_weff(const float* __restrict__ w_out) {
    const int h = blockIdx.x, b = blockIdx.y;
    const int bh = b * HEADS_ + h;
    const int t = threadIdx.x;

    __shared__ float ctxs[32][33];
    __shared__ float ws[256][33];

    // reduce 32 partials
    const float* pp = g_ctxp + (size_t)bh * 32 * (D_ * D_);
#pragma unroll
    for (int i = 0; i < 4; i++) {
        int elem = t + i * 256;
        float s = 0.f;
#pragma unroll
        for (int pg = 0; pg < 32; pg++) s += pp[pg * (D_ * D_) + elem];
        ctxs[elem >> 5][elem & 31] = s;
    }
    // stage w_out[:, h*32 : h*32+32]
#pragma unroll
    for (int i = 0; i < 32; i++) {
        int idx = t + i * 256;
        int r = idx >> 5, c = idx & 31;
        ws[r][c] = w_out[(size_t)r * C_ + h * D_ + c];
    }
    __syncthreads();

    float we[32] = {};
#pragma unroll
    for (int d = 0; d < 32; d++) {
        float wv = ws[t][d];
#pragma unroll
        for (int e = 0; e < 32; e++) we[e] += wv * ctxs[d][e];
    }
    float* op = g_weff + ((size_t)b * C_ + t) * C_ + h * D_;
#pragma unroll
    for (int e4 = 0; e4 < 8; e4++)
        *(float4*)&op[e4 * 4] = make_float4(we[e4 * 4], we[e4 * 4 + 1], we[e4 * 4 + 2], we[e4 * 4 + 3]);
}

// =====================================================================
// Kernel 4: out = w_eff[b] @ qhat + b_out, fused channel LayerNorm (tf32 MMA)
// block tile 256(M) x 64(N) x 32(K); 8 warps (4x2).
// =====================================================================
__global__ void __launch_bounds__(256) k_out_ln_tf32(const float* __restrict__ b_out,
                                                     const float* __restrict__ gamma,
                                                     const float* __restrict__ beta,
                                                     float* __restrict__ out) {
    __shared__ unsigned As[256][36];
    __shared__ unsigned Bs[32][72];
    __shared__ float s_sum[64], s_sq[64], s_mu[64], s_rs[64];

    const int tid  = threadIdx.x;
    const int warp = tid >> 5, lane = tid & 31;
    const int g = lane >> 2, tg = lane & 3;
    const int wm = warp >> 1, wn = warp & 1;

    const int blk = blockIdx.x;
    const int b   = blk >> 6;
    const int p0  = (blk & 63) * 64;

    const float* ab = g_qkv + (size_t)b * (3 * C_ * HW_) + p0;   // qhat section
    const float* wb = g_weff + (size_t)b * C_ * C_;

    if (tid < 64) { s_sum[tid] = 0.f; s_sq[tid] = 0.f; }

    float acc[4][4][4] = {};

    for (int k0 = 0; k0 < C_; k0 += 32) {
#pragma unroll
        for (int i = 0; i < 32; i++) {
            int idx = tid + i * 256;
            int r = idx >> 5, c = idx & 31;
            As[r][c] = f2tf32(wb[(size_t)r * C_ + k0 + c]);
        }
#pragma unroll
        for (int i = 0; i < 8; i++) {
            int idx = tid + i * 256;
            int r = idx >> 6, c = idx & 63;
            Bs[r][c] = f2tf32(ab[(size_t)(k0 + r) * HW_ + c]);
        }
        __syncthreads();

#pragma unroll
        for (int ks = 0; ks < 4; ks++) {
            const int kb = ks * 8;
            unsigned af[4][4], bf[4][2];
#pragma unroll
            for (int mt = 0; mt < 4; mt++) {
                int rm = wm * 64 + mt * 16;
                af[mt][0] = As[rm + g][kb + tg];
                af[mt][1] = As[rm + g + 8][kb + tg];
                af[mt][2] = As[rm + g][kb + tg + 4];
                af[mt][3] = As[rm + g + 8][kb + tg + 4];
            }
#pragma unroll
            for (int nt = 0; nt < 4; nt++) {
                int cn = wn * 32 + nt * 8 + g;
                bf[nt][0] = Bs[kb + tg][cn];
                bf[nt][1] = Bs[kb + tg + 4][cn];
            }
#pragma unroll
            for (int mt = 0; mt < 4; mt++)
#pragma unroll
                for (int nt = 0; nt < 4; nt++)
                    mma_tf32(acc[mt][nt], af[mt], bf[nt]);
        }
        __syncthreads();
    }

    float bias0[4], bias1[4], gam0[4], gam1[4], bet0[4], bet1[4];
#pragma unroll
    for (int mt = 0; mt < 4; mt++) {
        int r = wm * 64 + mt * 16 + g;
        bias0[mt] = b_out[r]; bias1[mt] = b_out[r + 8];
        gam0[mt]  = gamma[r]; gam1[mt]  = gamma[r + 8];
        bet0[mt]  = beta[r];  bet1[mt]  = beta[r + 8];
    }
#pragma unroll
    for (int mt = 0; mt < 4; mt++)
#pragma unroll
        for (int nt = 0; nt < 4; nt++) {
            acc[mt][nt][0] += bias0[mt]; acc[mt][nt][1] += bias0[mt];
            acc[mt][nt][2] += bias1[mt]; acc[mt][nt][3] += bias1[mt];
        }

#pragma unroll
    for (int nt = 0; nt < 4; nt++) {
        float s0 = 0.f, s1 = 0.f, q0 = 0.f, q1 = 0.f;
#pragma unroll
        for (int mt = 0; mt < 4; mt++) {
            float v0 = acc[mt][nt][0], v1 = acc[mt][nt][1];
            float v2 = acc[mt][nt][2], v3 = acc[mt][nt][3];
            s0 += v0 + v2; s1 += v1 + v3;
            q0 += v0 * v0 + v2 * v2; q1 += v1 * v1 + v3 * v3;
        }
#pragma unroll
        for (int off = 4; off < 32; off <<= 1) {
            s0 += __shfl_xor_sync(0xffffffffu, s0, off);
            s1 += __shfl_xor_sync(0xffffffffu, s1, off);
            q0 += __shfl_xor_sync(0xffffffffu, q0, off);
            q1 += __shfl_xor_sync(0xffffffffu, q1, off);
        }
        if (g == 0) {
            int c = wn * 32 + nt * 8 + tg * 2;
            atomicAdd(&s_sum[c], s0);     atomicAdd(&s_sq[c], q0);
            atomicAdd(&s_sum[c + 1], s1); atomicAdd(&s_sq[c + 1], q1);
        }
    }
    __syncthreads();

    if (tid < 64) {
        float mu  = s_sum[tid] * (1.0f / 256.0f);
        float var = s_sq[tid] * (1.0f / 256.0f) - mu * mu;
        s_mu[tid] = mu;
        s_rs[tid] = rsqrtf(var + LN_EPS);
    }
    __syncthreads();

    float* ob = out + (size_t)b * (C_ * HW_) + p0;
#pragma unroll
    for (int mt = 0; mt < 4; mt++) {
        int r = wm * 64 + mt * 16 + g;
#pragma unroll
        for (int nt = 0; nt < 4; nt++) {
            int c = wn * 32 + nt * 8 + tg * 2;
            float mu0 = s_mu[c], rs0 = s_rs[c];
            float mu1 = s_mu[c + 1], rs1 = s_rs[c + 1];
            float o0 = (acc[mt][nt][0] - mu0) * rs0 * gam0[mt] + bet0[mt];
            float o1 = (acc[mt][nt][1] - mu1) * rs1 * gam0[mt] + bet0[mt];
            float o2 = (acc[mt][nt][2] - mu0) * rs0 * gam1[mt] + bet1[mt];
            float o3 = (acc[mt][nt][3] - mu1) * rs1 * gam1[mt] + bet1[mt];
            *(float2*)&ob[(size_t)r * HW_ + c]       = make_float2(o0, o1);
            *(float2*)&ob[(size_t)(r + 8) * HW_ + c] = make_float2(o2, o3);
        }
    }
}

// =====================================================================
extern "C" void kernel_launch(void* const* d_in, const int* in_sizes, int n_in,
                              void* d_out, int out_size) {
    const float* x      = (const float*)d_in[0];
    const float* w_qkv  = (const float*)d_in[1];
    const float* w_out  = (const float*)d_in[2];
    const float* b_out  = (const float*)d_in[3];
    const float* gamma  = (const float*)d_in[4];
    const float* beta   = (const float*)d_in[5];
    float* out = (float*)d_out;

    dim3 g1((B_ * HW_) / 128, (3 * C_) / 128);    // 512 x 6
    k_qkv_gemm_tf32<<<g1, 256>>>(x, w_qkv);

    dim3 g2(8, B_ * HEADS_);                      // 8 splits x 128 (b,h)
    k_context<<<g2, 256>>>();

    dim3 g3(HEADS_, B_);                          // 8 x 16
    k_weff<<<g3, 256>>>(w_out);

    k_out_ln_tf32<<<(B_ * HW_) / 64, 256>>>(b_out, gamma, beta, out);
}

// round 4
// speedup vs baseline: 3.4593x; 1.3882x over previous
#include <cuda_runtime.h>

// ---------------- problem constants ----------------
#define B_      16
#define C_      256
#define HEADS_  8
#define D_      32          // dim_head
#define HW_     4096        // 64*64
#define W_      64
#define LN_EPS  1e-5f

// ---------------- scratch (no allocations allowed) ----------------
__device__ float    g_qkv[(size_t)B_ * 3 * C_ * HW_];  // qhat(tf32bits) | khat | v
__device__ float    g_ctxp[128 * 32 * (D_ * D_)];      // context partials
__device__ unsigned g_weff[(size_t)B_ * C_ * C_];      // w_eff as tf32 bit patterns

// ---------------- helpers ----------------
__device__ __forceinline__ unsigned f2tf32(float f) {
    unsigned u;
    asm("cvt.rna.tf32.f32 %0, %1;" : "=r"(u) : "f"(f));
    return u;
}

__device__ __forceinline__ void mma_tf32(float* c, const unsigned* a, const unsigned* b) {
    asm volatile(
        "mma.sync.aligned.m16n8k8.row.col.f32.tf32.tf32.f32 "
        "{%0,%1,%2,%3}, {%4,%5,%6,%7}, {%8,%9}, {%0,%1,%2,%3};"
        : "+f"(c[0]), "+f"(c[1]), "+f"(c[2]), "+f"(c[3])
        : "r"(a[0]), "r"(a[1]), "r"(a[2]), "r"(a[3]), "r"(b[0]), "r"(b[1]));
}

__device__ __forceinline__ void cp16(void* sdst, const void* gsrc) {
    unsigned d = (unsigned)__cvta_generic_to_shared(sdst);
    asm volatile("cp.async.cg.shared.global [%0], [%1], 16;" :: "r"(d), "l"(gsrc));
}
#define CP_COMMIT()  asm volatile("cp.async.commit_group;")
#define CP_WAIT(n)   asm volatile("cp.async.wait_group %0;" :: "n"(n))

// ---------------- dynamic smem layouts ----------------
struct QkvSmem {
    float As[2][128][36];    // [m][k], pad 36 -> frag bank (4g+tg) bijective
    float Bs[2][32][136];    // [k][n], pad 136 -> frag bank (8tg+g) bijective
    float red[2][4][128];    // k-softmax partials
};
struct OutSmem {
    unsigned As[2][256][36];
    unsigned Bs[2][32][72];  // pad 72 -> (8tg+g) bijective
    float s_sum[64], s_sq[64], s_mu[64], s_rs[64];
};

// =====================================================================
// Kernel 1: qkv = w_qkv @ x  (tf32 MMA, 128x128x32 tiles, 8 warps 2x4)
// cp.async 2-stage pipeline; cvt at fragment-load (fma pipe, overlaps tensor).
// Fused epilogues: q-softmax(d=32), k-softmax(y=64); q stored as tf32 bits.
// =====================================================================
__global__ void __launch_bounds__(256) k_qkv_gemm_tf32(const float* __restrict__ x,
                                                       const float* __restrict__ w) {
    extern __shared__ char smem_raw[];
    QkvSmem& S = *reinterpret_cast<QkvSmem*>(smem_raw);

    const int tid  = threadIdx.x;
    const int warp = tid >> 5, lane = tid & 31;
    const int g = lane >> 2, tg = lane & 3;
    const int wm = warp >> 2, wn = warp & 3;

    const int m0 = blockIdx.y * 128;
    const size_t n0 = (size_t)blockIdx.x * 128;
    const int b  = (int)(n0 >> 12);
    const int p0 = (int)(n0 & 4095);

    const float* xb = x + (size_t)b * (C_ * HW_) + p0;
    float* ob = g_qkv + (size_t)b * (3 * C_ * HW_) + p0;

    float acc[4][4][4] = {};

    // ---- pipeline prologue: stage 0
    {
#pragma unroll
        for (int i = 0; i < 4; i++) {
            int f4 = tid + i * 256;
            int ra = f4 >> 3, ca = (f4 & 7) << 2;
            cp16(&S.As[0][ra][ca], &w[(size_t)(m0 + ra) * C_ + ca]);
            int rb = f4 >> 5, cb = (f4 & 31) << 2;
            cp16(&S.Bs[0][rb][cb], &xb[(size_t)rb * HW_ + cb]);
        }
        CP_COMMIT();
    }

    int buf = 0;
    for (int k0 = 0; k0 < C_; k0 += 32) {
        if (k0 + 32 < C_) {
#pragma unroll
            for (int i = 0; i < 4; i++) {
                int f4 = tid + i * 256;
                int ra = f4 >> 3, ca = (f4 & 7) << 2;
                cp16(&S.As[buf ^ 1][ra][ca], &w[(size_t)(m0 + ra) * C_ + k0 + 32 + ca]);
                int rb = f4 >> 5, cb = (f4 & 31) << 2;
                cp16(&S.Bs[buf ^ 1][rb][cb], &xb[(size_t)(k0 + 32 + rb) * HW_ + cb]);
            }
            CP_COMMIT();
            CP_WAIT(1);
        } else {
            CP_WAIT(0);
        }
        __syncthreads();

#pragma unroll
        for (int ks = 0; ks < 4; ks++) {
            const int kb = ks * 8;
            unsigned af[4][4], bf[4][2];
#pragma unroll
            for (int mt = 0; mt < 4; mt++) {
                int rm = wm * 64 + mt * 16;
                af[mt][0] = f2tf32(S.As[buf][rm + g][kb + tg]);
                af[mt][1] = f2tf32(S.As[buf][rm + g + 8][kb + tg]);
                af[mt][2] = f2tf32(S.As[buf][rm + g][kb + tg + 4]);
                af[mt][3] = f2tf32(S.As[buf][rm + g + 8][kb + tg + 4]);
            }
#pragma unroll
            for (int nt = 0; nt < 4; nt++) {
                int cn = wn * 32 + nt * 8 + g;
                bf[nt][0] = f2tf32(S.Bs[buf][kb + tg][cn]);
                bf[nt][1] = f2tf32(S.Bs[buf][kb + tg + 4][cn]);
            }
#pragma unroll
            for (int mt = 0; mt < 4; mt++)
#pragma unroll
                for (int nt = 0; nt < 4; nt++)
                    mma_tf32(acc[mt][nt], af[mt], bf[nt]);
        }
        __syncthreads();
        buf ^= 1;
    }

    const int sect = blockIdx.y >> 1;   // 0=q, 1=k, 2=v

    if (sect == 0) {
        // q-softmax over d=32 (head = mt-pair; rows span g via shfl)
#pragma unroll
        for (int p = 0; p < 2; p++) {
#pragma unroll
            for (int nt = 0; nt < 4; nt++) {
#pragma unroll
                for (int j = 0; j < 2; j++) {
                    float v0 = acc[2 * p][nt][j],     v1 = acc[2 * p][nt][j + 2];
                    float v2 = acc[2 * p + 1][nt][j], v3 = acc[2 * p + 1][nt][j + 2];
                    float m = fmaxf(fmaxf(v0, v1), fmaxf(v2, v3));
                    m = fmaxf(m, __shfl_xor_sync(0xffffffffu, m, 4));
                    m = fmaxf(m, __shfl_xor_sync(0xffffffffu, m, 8));
                    m = fmaxf(m, __shfl_xor_sync(0xffffffffu, m, 16));
                    float e0 = __expf(v0 - m), e1 = __expf(v1 - m);
                    float e2 = __expf(v2 - m), e3 = __expf(v3 - m);
                    float s = e0 + e1 + e2 + e3;
                    s += __shfl_xor_sync(0xffffffffu, s, 4);
                    s += __shfl_xor_sync(0xffffffffu, s, 8);
                    s += __shfl_xor_sync(0xffffffffu, s, 16);
                    float inv = 1.0f / s;
                    acc[2 * p][nt][j]         = e0 * inv;
                    acc[2 * p][nt][j + 2]     = e1 * inv;
                    acc[2 * p + 1][nt][j]     = e2 * inv;
                    acc[2 * p + 1][nt][j + 2] = e3 * inv;
                }
            }
        }
        // store as tf32 bit patterns (out_ln consumes raw)
#pragma unroll
        for (int mt = 0; mt < 4; mt++)
#pragma unroll
            for (int nt = 0; nt < 4; nt++)
#pragma unroll
                for (int j = 0; j < 4; j++)
                    acc[mt][nt][j] = __uint_as_float(f2tf32(acc[mt][nt][j]));
    } else if (sect == 1) {
        // k-softmax over y=64: warp owns 32 cols; partner warp = wn^1
        float mloc[4][2], sloc[4][2];
#pragma unroll
        for (int mt = 0; mt < 4; mt++)
#pragma unroll
            for (int hf = 0; hf < 2; hf++) {
                float m = -1e30f;
#pragma unroll
                for (int nt = 0; nt < 4; nt++) {
                    m = fmaxf(m, acc[mt][nt][hf * 2]);
                    m = fmaxf(m, acc[mt][nt][hf * 2 + 1]);
                }
                m = fmaxf(m, __shfl_xor_sync(0xffffffffu, m, 1));
                m = fmaxf(m, __shfl_xor_sync(0xffffffffu, m, 2));
                mloc[mt][hf] = m;
                if (tg == 0) S.red[0][wn][wm * 64 + mt * 16 + hf * 8 + g] = m;
            }
        __syncthreads();
#pragma unroll
        for (int mt = 0; mt < 4; mt++)
#pragma unroll
            for (int hf = 0; hf < 2; hf++) {
                int ri = wm * 64 + mt * 16 + hf * 8 + g;
                float m = fmaxf(mloc[mt][hf], S.red[0][wn ^ 1][ri]);
                float s = 0.f;
#pragma unroll
                for (int nt = 0; nt < 4; nt++) {
                    float e0 = __expf(acc[mt][nt][hf * 2] - m);
                    float e1 = __expf(acc[mt][nt][hf * 2 + 1] - m);
                    acc[mt][nt][hf * 2]     = e0;
                    acc[mt][nt][hf * 2 + 1] = e1;
                    s += e0 + e1;
                }
                s += __shfl_xor_sync(0xffffffffu, s, 1);
                s += __shfl_xor_sync(0xffffffffu, s, 2);
                sloc[mt][hf] = s;
                if (tg == 0) S.red[1][wn][ri] = s;
            }
        __syncthreads();
#pragma unroll
        for (int mt = 0; mt < 4; mt++)
#pragma unroll
            for (int hf = 0; hf < 2; hf++) {
                int ri = wm * 64 + mt * 16 + hf * 8 + g;
                float inv = 1.0f / (sloc[mt][hf] + S.red[1][wn ^ 1][ri]);
#pragma unroll
                for (int nt = 0; nt < 4; nt++) {
                    acc[mt][nt][hf * 2]     *= inv;
                    acc[mt][nt][hf * 2 + 1] *= inv;
                }
            }
    }

#pragma unroll
    for (int mt = 0; mt < 4; mt++) {
        int r0 = m0 + wm * 64 + mt * 16 + g;
#pragma unroll
        for (int nt = 0; nt < 4; nt++) {
            int c = wn * 32 + nt * 8 + tg * 2;
            *(float2*)&ob[(size_t)r0 * HW_ + c]       = make_float2(acc[mt][nt][0], acc[mt][nt][1]);
            *(float2*)&ob[(size_t)(r0 + 8) * HW_ + c] = make_float2(acc[mt][nt][2], acc[mt][nt][3]);
        }
    }
}

// =====================================================================
// Kernel 2: context partials (fp32, memory-bound). grid (8 splits, 128 bh).
// =====================================================================
__global__ void __launch_bounds__(256) k_context() {
    const int s  = blockIdx.x;
    const int bh = blockIdx.y;
    const int b = bh >> 3, h = bh & 7;

    __shared__ float ks[128][36];
    __shared__ float vs[128][36];

    const float* kb = g_qkv + (size_t)b * (3 * C_ * HW_) + (size_t)(C_     + h * D_) * HW_;
    const float* vb = g_qkv + (size_t)b * (3 * C_ * HW_) + (size_t)(2 * C_ + h * D_) * HW_;

    const int t = threadIdx.x;
    const int ppg = t >> 6;
    const int t64 = t & 63;
    const int td = t64 >> 3, te = t64 & 7;

    float acc[4][4] = {};

    for (int chunk = 0; chunk < 4; chunk++) {
        const int pc = s * 512 + chunk * 128;
#pragma unroll
        for (int i = 0; i < 4; i++) {
            int idx = t + i * 256;
            int r = idx >> 5, c4 = idx & 31;
            float4 kv = *(const float4*)&kb[(size_t)r * HW_ + pc + c4 * 4];
            float4 vv = *(const float4*)&vb[(size_t)r * HW_ + pc + c4 * 4];
            ks[c4 * 4 + 0][r] = kv.x; ks[c4 * 4 + 1][r] = kv.y;
            ks[c4 * 4 + 2][r] = kv.z; ks[c4 * 4 + 3][r] = kv.w;
            vs[c4 * 4 + 0][r] = vv.x; vs[c4 * 4 + 1][r] = vv.y;
            vs[c4 * 4 + 2][r] = vv.z; vs[c4 * 4 + 3][r] = vv.w;
        }
        __syncthreads();
#pragma unroll 4
        for (int pp = ppg; pp < 128; pp += 4) {
            float4 ka = *(const float4*)&ks[pp][td * 4];
            float4 va = *(const float4*)&vs[pp][te * 4];
            const float* kp = &ka.x;
            const float* vp = &va.x;
#pragma unroll
            for (int i = 0; i < 4; i++)
#pragma unroll
                for (int j = 0; j < 4; j++)
                    acc[i][j] += kp[i] * vp[j];
        }
        __syncthreads();
    }

    float* op = g_ctxp + ((size_t)bh * 32 + s * 4 + ppg) * (D_ * D_);
#pragma unroll
    for (int i = 0; i < 4; i++)
        *(float4*)&op[(td * 4 + i) * D_ + te * 4] =
            make_float4(acc[i][0], acc[i][1], acc[i][2], acc[i][3]);
}

// =====================================================================
// Kernel 3: reduce ctx partials + w_eff = w_out(head slice) @ ctx, store tf32 bits
// =====================================================================
__global__ void __launch_bounds__(256) k_weff(const float* __restrict__ w_out) {
    const int h = blockIdx.x, b = blockIdx.y;
    const int bh = b * HEADS_ + h;
    const int t = threadIdx.x;

    __shared__ float ctxs[32][33];
    __shared__ float ws[256][33];

    const float* pp = g_ctxp + (size_t)bh * 32 * (D_ * D_);
#pragma unroll
    for (int i = 0; i < 4; i++) {
        int elem = t + i * 256;
        float s = 0.f;
#pragma unroll
        for (int pg = 0; pg < 32; pg++) s += pp[pg * (D_ * D_) + elem];
        ctxs[elem >> 5][elem & 31] = s;
    }
#pragma unroll
    for (int i = 0; i < 32; i++) {
        int idx = t + i * 256;
        int r = idx >> 5, c = idx & 31;
        ws[r][c] = w_out[(size_t)r * C_ + h * D_ + c];
    }
    __syncthreads();

    float we[32] = {};
#pragma unroll
    for (int d = 0; d < 32; d++) {
        float wv = ws[t][d];
#pragma unroll
        for (int e = 0; e < 32; e++) we[e] += wv * ctxs[d][e];
    }
    unsigned* op = g_weff + ((size_t)b * C_ + t) * C_ + h * D_;
#pragma unroll
    for (int e4 = 0; e4 < 8; e4++) {
        uint4 u = make_uint4(f2tf32(we[e4 * 4]), f2tf32(we[e4 * 4 + 1]),
                             f2tf32(we[e4 * 4 + 2]), f2tf32(we[e4 * 4 + 3]));
        *(uint4*)&op[e4 * 4] = u;
    }
}

// =====================================================================
// Kernel 4: out = w_eff[b] @ qhat + b_out, fused channel LayerNorm.
// Operands are pre-tf32 bits -> zero-CVT mainloop, cp.async 2-stage.
// block tile 256(M) x 64(N) x 32(K); 8 warps (4x2).
// =====================================================================
__global__ void __launch_bounds__(256) k_out_ln_tf32(const float* __restrict__ b_out,
                                                     const float* __restrict__ gamma,
                                                     const float* __restrict__ beta,
                                                     float* __restrict__ out) {
    extern __shared__ char smem_raw[];
    OutSmem& S = *reinterpret_cast<OutSmem*>(smem_raw);

    const int tid  = threadIdx.x;
    const int warp = tid >> 5, lane = tid & 31;
    const int g = lane >> 2, tg = lane & 3;
    const int wm = warp >> 1, wn = warp & 1;

    const int blk = blockIdx.x;
    const int b   = blk >> 6;
    const int p0  = (blk & 63) * 64;

    const float*    ab = g_qkv + (size_t)b * (3 * C_ * HW_) + p0;  // qhat (tf32 bits)
    const unsigned* wb = g_weff + (size_t)b * C_ * C_;

    if (tid < 64) { S.s_sum[tid] = 0.f; S.s_sq[tid] = 0.f; }

    float acc[4][4][4] = {};

    // prologue: stage 0
    {
#pragma unroll
        for (int i = 0; i < 8; i++) {
            int f4 = tid + i * 256;
            int ra = f4 >> 3, ca = (f4 & 7) << 2;
            cp16(&S.As[0][ra][ca], &wb[(size_t)ra * C_ + ca]);
        }
#pragma unroll
        for (int i = 0; i < 2; i++) {
            int f4 = tid + i * 256;
            int rb = f4 >> 4, cb = (f4 & 15) << 2;
            cp16(&S.Bs[0][rb][cb], &ab[(size_t)rb * HW_ + cb]);
        }
        CP_COMMIT();
    }

    int buf = 0;
    for (int k0 = 0; k0 < C_; k0 += 32) {
        if (k0 + 32 < C_) {
#pragma unroll
            for (int i = 0; i < 8; i++) {
                int f4 = tid + i * 256;
                int ra = f4 >> 3, ca = (f4 & 7) << 2;
                cp16(&S.As[buf ^ 1][ra][ca], &wb[(size_t)ra * C_ + k0 + 32 + ca]);
            }
#pragma unroll
            for (int i = 0; i < 2; i++) {
                int f4 = tid + i * 256;
                int rb = f4 >> 4, cb = (f4 & 15) << 2;
                cp16(&S.Bs[buf ^ 1][rb][cb], &ab[(size_t)(k0 + 32 + rb) * HW_ + cb]);
            }
            CP_COMMIT();
            CP_WAIT(1);
        } else {
            CP_WAIT(0);
        }
        __syncthreads();

#pragma unroll
        for (int ks = 0; ks < 4; ks++) {
            const int kb = ks * 8;
            unsigned af[4][4], bf[4][2];
#pragma unroll
            for (int mt = 0; mt < 4; mt++) {
                int rm = wm * 64 + mt * 16;
                af[mt][0] = S.As[buf][rm + g][kb + tg];
                af[mt][1] = S.As[buf][rm + g + 8][kb + tg];
                af[mt][2] = S.As[buf][rm + g][kb + tg + 4];
                af[mt][3] = S.As[buf][rm + g + 8][kb + tg + 4];
            }
#pragma unroll
            for (int nt = 0; nt < 4; nt++) {
                int cn = wn * 32 + nt * 8 + g;
                bf[nt][0] = S.Bs[buf][kb + tg][cn];
                bf[nt][1] = S.Bs[buf][kb + tg + 4][cn];
            }
#pragma unroll
            for (int mt = 0; mt < 4; mt++)
#pragma unroll
                for (int nt = 0; nt < 4; nt++)
                    mma_tf32(acc[mt][nt], af[mt], bf[nt]);
        }
        __syncthreads();
        buf ^= 1;
    }

    float bias0[4], bias1[4], gam0[4], gam1[4], bet0[4], bet1[4];
#pragma unroll
    for (int mt = 0; mt < 4; mt++) {
        int r = wm * 64 + mt * 16 + g;
        bias0[mt] = b_out[r]; bias1[mt] = b_out[r + 8];
        gam0[mt]  = gamma[r]; gam1[mt]  = gamma[r + 8];
        bet0[mt]  = beta[r];  bet1[mt]  = beta[r + 8];
    }
#pragma unroll
    for (int mt = 0; mt < 4; mt++)
#pragma unroll
        for (int nt = 0; nt < 4; nt++) {
            acc[mt][nt][0] += bias0[mt]; acc[mt][nt][1] += bias0[mt];
            acc[mt][nt][2] += bias1[mt]; acc[mt][nt][3] += bias1[mt];
        }

#pragma unroll
    for (int nt = 0; nt < 4; nt++) {
        float s0 = 0.f, s1 = 0.f, q0 = 0.f, q1 = 0.f;
#pragma unroll
        for (int mt = 0; mt < 4; mt++) {
            float v0 = acc[mt][nt][0], v1 = acc[mt][nt][1];
            float v2 = acc[mt][nt][2], v3 = acc[mt][nt][3];
            s0 += v0 + v2; s1 += v1 + v3;
            q0 += v0 * v0 + v2 * v2; q1 += v1 * v1 + v3 * v3;
        }
#pragma unroll
        for (int off = 4; off < 32; off <<= 1) {
            s0 += __shfl_xor_sync(0xffffffffu, s0, off);
            s1 += __shfl_xor_sync(0xffffffffu, s1, off);
            q0 += __shfl_xor_sync(0xffffffffu, q0, off);
            q1 += __shfl_xor_sync(0xffffffffu, q1, off);
        }
        if (g == 0) {
            int c = wn * 32 + nt * 8 + tg * 2;
            atomicAdd(&S.s_sum[c], s0);     atomicAdd(&S.s_sq[c], q0);
            atomicAdd(&S.s_sum[c + 1], s1); atomicAdd(&S.s_sq[c + 1], q1);
        }
    }
    __syncthreads();

    if (tid < 64) {
        float mu  = S.s_sum[tid] * (1.0f / 256.0f);
        float var = S.s_sq[tid] * (1.0f / 256.0f) - mu * mu;
        S.s_mu[tid] = mu;
        S.s_rs[tid] = rsqrtf(var + LN_EPS);
    }
    __syncthreads();

    float* ob = out + (size_t)b * (C_ * HW_) + p0;
#pragma unroll
    for (int mt = 0; mt < 4; mt++) {
        int r = wm * 64 + mt * 16 + g;
#pragma unroll
        for (int nt = 0; nt < 4; nt++) {
            int c = wn * 32 + nt * 8 + tg * 2;
            float mu0 = S.s_mu[c], rs0 = S.s_rs[c];
            float mu1 = S.s_mu[c + 1], rs1 = S.s_rs[c + 1];
            float o0 = (acc[mt][nt][0] - mu0) * rs0 * gam0[mt] + bet0[mt];
            float o1 = (acc[mt][nt][1] - mu1) * rs1 * gam0[mt] + bet0[mt];
            float o2 = (acc[mt][nt][2] - mu0) * rs0 * gam1[mt] + bet1[mt];
            float o3 = (acc[mt][nt][3] - mu1) * rs1 * gam1[mt] + bet1[mt];
            *(float2*)&ob[(size_t)r * HW_ + c]       = make_float2(o0, o1);
            *(float2*)&ob[(size_t)(r + 8) * HW_ + c] = make_float2(o2, o3);
        }
    }
}

// =====================================================================
extern "C" void kernel_launch(void* const* d_in, const int* in_sizes, int n_in,
                              void* d_out, int out_size) {
    const float* x      = (const float*)d_in[0];
    const float* w_qkv  = (const float*)d_in[1];
    const float* w_out  = (const float*)d_in[2];
    const float* b_out  = (const float*)d_in[3];
    const float* gamma  = (const float*)d_in[4];
    const float* beta   = (const float*)d_in[5];
    float* out = (float*)d_out;

    cudaFuncSetAttribute(k_qkv_gemm_tf32, cudaFuncAttributeMaxDynamicSharedMemorySize,
                         (int)sizeof(QkvSmem));
    cudaFuncSetAttribute(k_out_ln_tf32, cudaFuncAttributeMaxDynamicSharedMemorySize,
                         (int)sizeof(OutSmem));

    dim3 g1((B_ * HW_) / 128, (3 * C_) / 128);    // 512 x 6
    k_qkv_gemm_tf32<<<g1, 256, sizeof(QkvSmem)>>>(x, w_qkv);

    dim3 g2(8, B_ * HEADS_);                      // 8 splits x 128 (b,h)
    k_context<<<g2, 256>>>();

    dim3 g3(HEADS_, B_);                          // 8 x 16
    k_weff<<<g3, 256>>>(w_out);

    k_out_ln_tf32<<<(B_ * HW_) / 64, 256, sizeof(OutSmem)>>>(b_out, gamma, beta, out);
}

// round 5
// speedup vs baseline: 4.1971x; 1.2133x over previous
#include <cuda_runtime.h>

// ---------------- problem constants ----------------
#define B_      16
#define C_      256
#define HEADS_  8
#define D_      32          // dim_head
#define HW_     4096        // 64*64
#define W_      64
#define LN_EPS  1e-5f

// ---------------- scratch (no allocations allowed) ----------------
__device__ float    g_q[(size_t)B_ * C_ * HW_];        // qhat as tf32 bit patterns
__device__ float    g_ctxp[(size_t)B_ * HEADS_ * 32 * (D_ * D_)]; // ctx partials per pixel-tile
__device__ unsigned g_weff[(size_t)B_ * C_ * C_];      // w_eff as tf32 bit patterns

// ---------------- helpers ----------------
__device__ __forceinline__ unsigned f2tf32(float f) {
    unsigned u;
    asm("cvt.rna.tf32.f32 %0, %1;" : "=r"(u) : "f"(f));
    return u;
}

__device__ __forceinline__ void mma_tf32(float* c, const unsigned* a, const unsigned* b) {
    asm volatile(
        "mma.sync.aligned.m16n8k8.row.col.f32.tf32.tf32.f32 "
        "{%0,%1,%2,%3}, {%4,%5,%6,%7}, {%8,%9}, {%0,%1,%2,%3};"
        : "+f"(c[0]), "+f"(c[1]), "+f"(c[2]), "+f"(c[3])
        : "r"(a[0]), "r"(a[1]), "r"(a[2]), "r"(a[3]), "r"(b[0]), "r"(b[1]));
}

__device__ __forceinline__ void cp16(void* sdst, const void* gsrc) {
    unsigned d = (unsigned)__cvta_generic_to_shared(sdst);
    asm volatile("cp.async.cg.shared.global [%0], [%1], 16;" :: "r"(d), "l"(gsrc));
}
#define CP_COMMIT()  asm volatile("cp.async.commit_group;")
#define CP_WAIT(n)   asm volatile("cp.async.wait_group %0;" :: "n"(n))

// ---------------- dynamic smem layouts ----------------
struct GemmBufs {
    float As[2][128][36];    // [m][k], pad 36
    float Bs[2][32][136];    // [k][n], pad 136
};
struct KvSmem {
    union {
        GemmBufs gb;
        float sc[128][132];  // [pixel][row] transposed tile for ctx compute
    } u;
    float red[2][4][64];     // k-softmax cross-warp partials (rows 0..63)
};
struct OutSmem {
    unsigned As[2][256][36];
    unsigned Bs[2][32][72];
    float s_sum[64], s_sq[64], s_mu[64], s_rs[64];
};

// =====================================================================
// Kernel 1: qhat = softmax_d(w_q @ x)   (tf32 MMA, 128x128x32 tiles)
// grid (512 pixel-tiles, 2 row-blocks); stores tf32 bit patterns.
// =====================================================================
__global__ void __launch_bounds__(256) k_q_gemm(const float* __restrict__ x,
                                                const float* __restrict__ w) {
    extern __shared__ char smem_raw[];
    GemmBufs& S = *reinterpret_cast<GemmBufs*>(smem_raw);

    const int tid  = threadIdx.x;
    const int warp = tid >> 5, lane = tid & 31;
    const int g = lane >> 2, tg = lane & 3;
    const int wm = warp >> 2, wn = warp & 3;

    const int m0 = blockIdx.y * 128;
    const size_t n0 = (size_t)blockIdx.x * 128;
    const int b  = (int)(n0 >> 12);
    const int p0 = (int)(n0 & 4095);

    const float* xb = x + (size_t)b * (C_ * HW_) + p0;
    float* ob = g_q + (size_t)b * (C_ * HW_) + p0;

    float acc[4][4][4] = {};

    {
#pragma unroll
        for (int i = 0; i < 4; i++) {
            int f4 = tid + i * 256;
            int ra = f4 >> 3, ca = (f4 & 7) << 2;
            cp16(&S.As[0][ra][ca], &w[(size_t)(m0 + ra) * C_ + ca]);
            int rb = f4 >> 5, cb = (f4 & 31) << 2;
            cp16(&S.Bs[0][rb][cb], &xb[(size_t)rb * HW_ + cb]);
        }
        CP_COMMIT();
    }

    int buf = 0;
    for (int k0 = 0; k0 < C_; k0 += 32) {
        if (k0 + 32 < C_) {
#pragma unroll
            for (int i = 0; i < 4; i++) {
                int f4 = tid + i * 256;
                int ra = f4 >> 3, ca = (f4 & 7) << 2;
                cp16(&S.As[buf ^ 1][ra][ca], &w[(size_t)(m0 + ra) * C_ + k0 + 32 + ca]);
                int rb = f4 >> 5, cb = (f4 & 31) << 2;
                cp16(&S.Bs[buf ^ 1][rb][cb], &xb[(size_t)(k0 + 32 + rb) * HW_ + cb]);
            }
            CP_COMMIT();
            CP_WAIT(1);
        } else {
            CP_WAIT(0);
        }
        __syncthreads();

#pragma unroll
        for (int ks = 0; ks < 4; ks++) {
            const int kb = ks * 8;
            unsigned af[4][4], bf[4][2];
#pragma unroll
            for (int mt = 0; mt < 4; mt++) {
                int rm = wm * 64 + mt * 16;
                af[mt][0] = f2tf32(S.As[buf][rm + g][kb + tg]);
                af[mt][1] = f2tf32(S.As[buf][rm + g + 8][kb + tg]);
                af[mt][2] = f2tf32(S.As[buf][rm + g][kb + tg + 4]);
                af[mt][3] = f2tf32(S.As[buf][rm + g + 8][kb + tg + 4]);
            }
#pragma unroll
            for (int nt = 0; nt < 4; nt++) {
                int cn = wn * 32 + nt * 8 + g;
                bf[nt][0] = f2tf32(S.Bs[buf][kb + tg][cn]);
                bf[nt][1] = f2tf32(S.Bs[buf][kb + tg + 4][cn]);
            }
#pragma unroll
            for (int mt = 0; mt < 4; mt++)
#pragma unroll
                for (int nt = 0; nt < 4; nt++)
                    mma_tf32(acc[mt][nt], af[mt], bf[nt]);
        }
        __syncthreads();
        buf ^= 1;
    }

    // q-softmax over d=32 (head = mt-pair; rows span g via shfl)
#pragma unroll
    for (int p = 0; p < 2; p++) {
#pragma unroll
        for (int nt = 0; nt < 4; nt++) {
#pragma unroll
            for (int j = 0; j < 2; j++) {
                float v0 = acc[2 * p][nt][j],     v1 = acc[2 * p][nt][j + 2];
                float v2 = acc[2 * p + 1][nt][j], v3 = acc[2 * p + 1][nt][j + 2];
                float m = fmaxf(fmaxf(v0, v1), fmaxf(v2, v3));
                m = fmaxf(m, __shfl_xor_sync(0xffffffffu, m, 4));
                m = fmaxf(m, __shfl_xor_sync(0xffffffffu, m, 8));
                m = fmaxf(m, __shfl_xor_sync(0xffffffffu, m, 16));
                float e0 = __expf(v0 - m), e1 = __expf(v1 - m);
                float e2 = __expf(v2 - m), e3 = __expf(v3 - m);
                float s = e0 + e1 + e2 + e3;
                s += __shfl_xor_sync(0xffffffffu, s, 4);
                s += __shfl_xor_sync(0xffffffffu, s, 8);
                s += __shfl_xor_sync(0xffffffffu, s, 16);
                float inv = 1.0f / s;
                acc[2 * p][nt][j]         = e0 * inv;
                acc[2 * p][nt][j + 2]     = e1 * inv;
                acc[2 * p + 1][nt][j]     = e2 * inv;
                acc[2 * p + 1][nt][j + 2] = e3 * inv;
            }
        }
    }
#pragma unroll
    for (int mt = 0; mt < 4; mt++)
#pragma unroll
        for (int nt = 0; nt < 4; nt++)
#pragma unroll
            for (int j = 0; j < 4; j++)
                acc[mt][nt][j] = __uint_as_float(f2tf32(acc[mt][nt][j]));

#pragma unroll
    for (int mt = 0; mt < 4; mt++) {
        int r0 = m0 + wm * 64 + mt * 16 + g;
#pragma unroll
        for (int nt = 0; nt < 4; nt++) {
            int c = wn * 32 + nt * 8 + tg * 2;
            *(float2*)&ob[(size_t)r0 * HW_ + c]       = make_float2(acc[mt][nt][0], acc[mt][nt][1]);
            *(float2*)&ob[(size_t)(r0 + 8) * HW_ + c] = make_float2(acc[mt][nt][2], acc[mt][nt][3]);
        }
    }
}

// =====================================================================
// Kernel 2: fused kv GEMM + k-softmax + per-head context partial.
// grid (4 head-pairs, 32 pixel-tiles, 16 batches); block 256 (8 warps 2x4).
// Tile M=128: rows 0-63 = khat(h0,h1), rows 64-127 = v(h0,h1); N=128 pixels.
// Writes ONLY 2x 32x32 fp32 context partials per block (k/v never hit DRAM).
// =====================================================================
__global__ void __launch_bounds__(256) k_kv_ctx(const float* __restrict__ x,
                                                const float* __restrict__ w) {
    extern __shared__ char smem_raw[];
    KvSmem& S = *reinterpret_cast<KvSmem*>(smem_raw);

    const int tid  = threadIdx.x;
    const int warp = tid >> 5, lane = tid & 31;
    const int g = lane >> 2, tg = lane & 3;
    const int wm = warp >> 2, wn = warp & 3;

    const int hp = blockIdx.x;          // head pair 0..3
    const int pt = blockIdx.y;          // pixel tile 0..31
    const int b  = blockIdx.z;
    const int p0 = pt * 128;

    const float* xb = x + (size_t)b * (C_ * HW_) + p0;

    float acc[4][4][4] = {};

    // A row map: r<64 -> k rows (C_ + hp*64 + r); else v rows (2C_ + hp*64 + r-64)
    {
#pragma unroll
        for (int i = 0; i < 4; i++) {
            int f4 = tid + i * 256;
            int ra = f4 >> 3, ca = (f4 & 7) << 2;
            int gr = (ra < 64) ? (C_ + hp * 64 + ra) : (2 * C_ + hp * 64 + ra - 64);
            cp16(&S.u.gb.As[0][ra][ca], &w[(size_t)gr * C_ + ca]);
            int rb = f4 >> 5, cb = (f4 & 31) << 2;
            cp16(&S.u.gb.Bs[0][rb][cb], &xb[(size_t)rb * HW_ + cb]);
        }
        CP_COMMIT();
    }

    int buf = 0;
    for (int k0 = 0; k0 < C_; k0 += 32) {
        if (k0 + 32 < C_) {
#pragma unroll
            for (int i = 0; i < 4; i++) {
                int f4 = tid + i * 256;
                int ra = f4 >> 3, ca = (f4 & 7) << 2;
                int gr = (ra < 64) ? (C_ + hp * 64 + ra) : (2 * C_ + hp * 64 + ra - 64);
                cp16(&S.u.gb.As[buf ^ 1][ra][ca], &w[(size_t)gr * C_ + k0 + 32 + ca]);
                int rb = f4 >> 5, cb = (f4 & 31) << 2;
                cp16(&S.u.gb.Bs[buf ^ 1][rb][cb], &xb[(size_t)(k0 + 32 + rb) * HW_ + cb]);
            }
            CP_COMMIT();
            CP_WAIT(1);
        } else {
            CP_WAIT(0);
        }
        __syncthreads();

#pragma unroll
        for (int ks = 0; ks < 4; ks++) {
            const int kb = ks * 8;
            unsigned af[4][4], bf[4][2];
#pragma unroll
            for (int mt = 0; mt < 4; mt++) {
                int rm = wm * 64 + mt * 16;
                af[mt][0] = f2tf32(S.u.gb.As[buf][rm + g][kb + tg]);
                af[mt][1] = f2tf32(S.u.gb.As[buf][rm + g + 8][kb + tg]);
                af[mt][2] = f2tf32(S.u.gb.As[buf][rm + g][kb + tg + 4]);
                af[mt][3] = f2tf32(S.u.gb.As[buf][rm + g + 8][kb + tg + 4]);
            }
#pragma unroll
            for (int nt = 0; nt < 4; nt++) {
                int cn = wn * 32 + nt * 8 + g;
                bf[nt][0] = f2tf32(S.u.gb.Bs[buf][kb + tg][cn]);
                bf[nt][1] = f2tf32(S.u.gb.Bs[buf][kb + tg + 4][cn]);
            }
#pragma unroll
            for (int mt = 0; mt < 4; mt++)
#pragma unroll
                for (int nt = 0; nt < 4; nt++)
                    mma_tf32(acc[mt][nt], af[mt], bf[nt]);
        }
        __syncthreads();
        buf ^= 1;
    }

    // ---- k-softmax over y=64 (rows 0-63, i.e. wm==0 warps only).
    // Warp wn owns 32 cols; partner wn^1 completes the 64-pixel y-row.
    float mloc[4][2], sloc[4][2];
    if (wm == 0) {
#pragma unroll
        for (int mt = 0; mt < 4; mt++)
#pragma unroll
            for (int hf = 0; hf < 2; hf++) {
                float m = -1e30f;
#pragma unroll
                for (int nt = 0; nt < 4; nt++) {
                    m = fmaxf(m, acc[mt][nt][hf * 2]);
                    m = fmaxf(m, acc[mt][nt][hf * 2 + 1]);
                }
                m = fmaxf(m, __shfl_xor_sync(0xffffffffu, m, 1));
                m = fmaxf(m, __shfl_xor_sync(0xffffffffu, m, 2));
                mloc[mt][hf] = m;
                if (tg == 0) S.red[0][wn][mt * 16 + hf * 8 + g] = m;
            }
    }
    __syncthreads();
    if (wm == 0) {
#pragma unroll
        for (int mt = 0; mt < 4; mt++)
#pragma unroll
            for (int hf = 0; hf < 2; hf++) {
                int ri = mt * 16 + hf * 8 + g;
                float m = fmaxf(mloc[mt][hf], S.red[0][wn ^ 1][ri]);
                float s = 0.f;
#pragma unroll
                for (int nt = 0; nt < 4; nt++) {
                    float e0 = __expf(acc[mt][nt][hf * 2] - m);
                    float e1 = __expf(acc[mt][nt][hf * 2 + 1] - m);
                    acc[mt][nt][hf * 2]     = e0;
                    acc[mt][nt][hf * 2 + 1] = e1;
                    s += e0 + e1;
                }
                s += __shfl_xor_sync(0xffffffffu, s, 1);
                s += __shfl_xor_sync(0xffffffffu, s, 2);
                sloc[mt][hf] = s;
                if (tg == 0) S.red[1][wn][ri] = s;
            }
    }
    __syncthreads();
    if (wm == 0) {
#pragma unroll
        for (int mt = 0; mt < 4; mt++)
#pragma unroll
            for (int hf = 0; hf < 2; hf++) {
                int ri = mt * 16 + hf * 8 + g;
                float inv = 1.0f / (sloc[mt][hf] + S.red[1][wn ^ 1][ri]);
#pragma unroll
                for (int nt = 0; nt < 4; nt++) {
                    acc[mt][nt][hf * 2]     *= inv;
                    acc[mt][nt][hf * 2 + 1] *= inv;
                }
            }
    }
    __syncthreads();   // mainloop smem reads done; safe to overwrite with sc

    // ---- store transposed [pixel][row] (banks: 8tg+g bijective, conflict-free)
#pragma unroll
    for (int mt = 0; mt < 4; mt++) {
        int r0 = wm * 64 + mt * 16 + g;
#pragma unroll
        for (int nt = 0; nt < 4; nt++) {
            int c = wn * 32 + nt * 8 + tg * 2;
            S.u.sc[c][r0]         = acc[mt][nt][0];
            S.u.sc[c + 1][r0]     = acc[mt][nt][1];
            S.u.sc[c][r0 + 8]     = acc[mt][nt][2];
            S.u.sc[c + 1][r0 + 8] = acc[mt][nt][3];
        }
    }
    __syncthreads();

    // ---- ctx partial: per head, ctx[d][e] = sum_p khat[d][p] * v[e][p]  (fp32)
    {
        const int h  = tid >> 7;            // head within pair
        const int tl = tid & 127;
        const int td = tl >> 3;             // 0..15 -> d = td*2
        const int te = tl & 7;              // 0..7  -> e = te*4
        const int d0 = h * 32 + td * 2;
        const int e0 = 64 + h * 32 + te * 4;

        float a00 = 0.f, a01 = 0.f, a02 = 0.f, a03 = 0.f;
        float a10 = 0.f, a11 = 0.f, a12 = 0.f, a13 = 0.f;
#pragma unroll 8
        for (int p = 0; p < 128; p++) {
            float2 kk = *(const float2*)&S.u.sc[p][d0];
            float4 vv = *(const float4*)&S.u.sc[p][e0];
            a00 += kk.x * vv.x; a01 += kk.x * vv.y; a02 += kk.x * vv.z; a03 += kk.x * vv.w;
            a10 += kk.y * vv.x; a11 += kk.y * vv.y; a12 += kk.y * vv.z; a13 += kk.y * vv.w;
        }
        float* op = g_ctxp + (((size_t)(b * HEADS_ + hp * 2 + h)) * 32 + pt) * (D_ * D_);
        *(float4*)&op[(td * 2 + 0) * D_ + te * 4] = make_float4(a00, a01, a02, a03);
        *(float4*)&op[(td * 2 + 1) * D_ + te * 4] = make_float4(a10, a11, a12, a13);
    }
}

// =====================================================================
// Kernel 3: reduce ctx partials + w_eff = w_out(head slice) @ ctx (tf32 bits)
// =====================================================================
__global__ void __launch_bounds__(256) k_weff(const float* __restrict__ w_out) {
    const int h = blockIdx.x, b = blockIdx.y;
    const int bh = b * HEADS_ + h;
    const int t = threadIdx.x;

    __shared__ float ctxs[32][33];
    __shared__ float ws[256][33];

    const float* pp = g_ctxp + (size_t)bh * 32 * (D_ * D_);
#pragma unroll
    for (int i = 0; i < 4; i++) {
        int elem = t + i * 256;
        float s = 0.f;
#pragma unroll
        for (int pg = 0; pg < 32; pg++) s += pp[pg * (D_ * D_) + elem];
        ctxs[elem >> 5][elem & 31] = s;
    }
#pragma unroll
    for (int i = 0; i < 32; i++) {
        int idx = t + i * 256;
        int r = idx >> 5, c = idx & 31;
        ws[r][c] = w_out[(size_t)r * C_ + h * D_ + c];
    }
    __syncthreads();

    float we[32] = {};
#pragma unroll
    for (int d = 0; d < 32; d++) {
        float wv = ws[t][d];
#pragma unroll
        for (int e = 0; e < 32; e++) we[e] += wv * ctxs[d][e];
    }
    unsigned* op = g_weff + ((size_t)b * C_ + t) * C_ + h * D_;
#pragma unroll
    for (int e4 = 0; e4 < 8; e4++) {
        uint4 u = make_uint4(f2tf32(we[e4 * 4]), f2tf32(we[e4 * 4 + 1]),
                             f2tf32(we[e4 * 4 + 2]), f2tf32(we[e4 * 4 + 3]));
        *(uint4*)&op[e4 * 4] = u;
    }
}

// =====================================================================
// Kernel 4: out = w_eff[b] @ qhat + b_out, fused channel LayerNorm.
// Pre-tf32-bit operands -> zero-CVT mainloop, cp.async 2-stage.
// =====================================================================
__global__ void __launch_bounds__(256) k_out_ln_tf32(const float* __restrict__ b_out,
                                                     const float* __restrict__ gamma,
                                                     const float* __restrict__ beta,
                                                     float* __restrict__ out) {
    extern __shared__ char smem_raw[];
    OutSmem& S = *reinterpret_cast<OutSmem*>(smem_raw);

    const int tid  = threadIdx.x;
    const int warp = tid >> 5, lane = tid & 31;
    const int g = lane >> 2, tg = lane & 3;
    const int wm = warp >> 1, wn = warp & 1;

    const int blk = blockIdx.x;
    const int b   = blk >> 6;
    const int p0  = (blk & 63) * 64;

    const float*    ab = g_q + (size_t)b * (C_ * HW_) + p0;   // qhat (tf32 bits)
    const unsigned* wb = g_weff + (size_t)b * C_ * C_;

    if (tid < 64) { S.s_sum[tid] = 0.f; S.s_sq[tid] = 0.f; }

    float acc[4][4][4] = {};

    {
#pragma unroll
        for (int i = 0; i < 8; i++) {
            int f4 = tid + i * 256;
            int ra = f4 >> 3, ca = (f4 & 7) << 2;
            cp16(&S.As[0][ra][ca], &wb[(size_t)ra * C_ + ca]);
        }
#pragma unroll
        for (int i = 0; i < 2; i++) {
            int f4 = tid + i * 256;
            int rb = f4 >> 4, cb = (f4 & 15) << 2;
            cp16(&S.Bs[0][rb][cb], &ab[(size_t)rb * HW_ + cb]);
        }
        CP_COMMIT();
    }

    int buf = 0;
    for (int k0 = 0; k0 < C_; k0 += 32) {
        if (k0 + 32 < C_) {
#pragma unroll
            for (int i = 0; i < 8; i++) {
                int f4 = tid + i * 256;
                int ra = f4 >> 3, ca = (f4 & 7) << 2;
                cp16(&S.As[buf ^ 1][ra][ca], &wb[(size_t)ra * C_ + k0 + 32 + ca]);
            }
#pragma unroll
            for (int i = 0; i < 2; i++) {
                int f4 = tid + i * 256;
                int rb = f4 >> 4, cb = (f4 & 15) << 2;
                cp16(&S.Bs[buf ^ 1][rb][cb], &ab[(size_t)(k0 + 32 + rb) * HW_ + cb]);
            }
            CP_COMMIT();
            CP_WAIT(1);
        } else {
            CP_WAIT(0);
        }
        __syncthreads();

#pragma unroll
        for (int ks = 0; ks < 4; ks++) {
            const int kb = ks * 8;
            unsigned af[4][4], bf[4][2];
#pragma unroll
            for (int mt = 0; mt < 4; mt++) {
                int rm = wm * 64 + mt * 16;
                af[mt][0] = S.As[buf][rm + g][kb + tg];
                af[mt][1] = S.As[buf][rm + g + 8][kb + tg];
                af[mt][2] = S.As[buf][rm + g][kb + tg + 4];
                af[mt][3] = S.As[buf][rm + g + 8][kb + tg + 4];
            }
#pragma unroll
            for (int nt = 0; nt < 4; nt++) {
                int cn = wn * 32 + nt * 8 + g;
                bf[nt][0] = S.Bs[buf][kb + tg][cn];
                bf[nt][1] = S.Bs[buf][kb + tg + 4][cn];
            }
#pragma unroll
            for (int mt = 0; mt < 4; mt++)
#pragma unroll
                for (int nt = 0; nt < 4; nt++)
                    mma_tf32(acc[mt][nt], af[mt], bf[nt]);
        }
        __syncthreads();
        buf ^= 1;
    }

    float bias0[4], bias1[4], gam0[4], gam1[4], bet0[4], bet1[4];
#pragma unroll
    for (int mt = 0; mt < 4; mt++) {
        int r = wm * 64 + mt * 16 + g;
        bias0[mt] = b_out[r]; bias1[mt] = b_out[r + 8];
        gam0[mt]  = gamma[r]; gam1[mt]  = gamma[r + 8];
        bet0[mt]  = beta[r];  bet1[mt]  = beta[r + 8];
    }
#pragma unroll
    for (int mt = 0; mt < 4; mt++)
#pragma unroll
        for (int nt = 0; nt < 4; nt++) {
            acc[mt][nt][0] += bias0[mt]; acc[mt][nt][1] += bias0[mt];
            acc[mt][nt][2] += bias1[mt]; acc[mt][nt][3] += bias1[mt];
        }

#pragma unroll
    for (int nt = 0; nt < 4; nt++) {
        float s0 = 0.f, s1 = 0.f, q0 = 0.f, q1 = 0.f;
#pragma unroll
        for (int mt = 0; mt < 4; mt++) {
            float v0 = acc[mt][nt][0], v1 = acc[mt][nt][1];
            float v2 = acc[mt][nt][2], v3 = acc[mt][nt][3];
            s0 += v0 + v2; s1 += v1 + v3;
            q0 += v0 * v0 + v2 * v2; q1 += v1 * v1 + v3 * v3;
        }
#pragma unroll
        for (int off = 4; off < 32; off <<= 1) {
            s0 += __shfl_xor_sync(0xffffffffu, s0, off);
            s1 += __shfl_xor_sync(0xffffffffu, s1, off);
            q0 += __shfl_xor_sync(0xffffffffu, q0, off);
            q1 += __shfl_xor_sync(0xffffffffu, q1, off);
        }
        if (g == 0) {
            int c = wn * 32 + nt * 8 + tg * 2;
            atomicAdd(&S.s_sum[c], s0);     atomicAdd(&S.s_sq[c], q0);
            atomicAdd(&S.s_sum[c + 1], s1); atomicAdd(&S.s_sq[c + 1], q1);
        }
    }
    __syncthreads();

    if (tid < 64) {
        float mu  = S.s_sum[tid] * (1.0f / 256.0f);
        float var = S.s_sq[tid] * (1.0f / 256.0f) - mu * mu;
        S.s_mu[tid] = mu;
        S.s_rs[tid] = rsqrtf(var + LN_EPS);
    }
    __syncthreads();

    float* ob = out + (size_t)b * (C_ * HW_) + p0;
#pragma unroll
    for (int mt = 0; mt < 4; mt++) {
        int r = wm * 64 + mt * 16 + g;
#pragma unroll
        for (int nt = 0; nt < 4; nt++) {
            int c = wn * 32 + nt * 8 + tg * 2;
            float mu0 = S.s_mu[c], rs0 = S.s_rs[c];
            float mu1 = S.s_mu[c + 1], rs1 = S.s_rs[c + 1];
            float o0 = (acc[mt][nt][0] - mu0) * rs0 * gam0[mt] + bet0[mt];
            float o1 = (acc[mt][nt][1] - mu1) * rs1 * gam0[mt] + bet0[mt];
            float o2 = (acc[mt][nt][2] - mu0) * rs0 * gam1[mt] + bet1[mt];
            float o3 = (acc[mt][nt][3] - mu1) * rs1 * gam1[mt] + bet1[mt];
            *(float2*)&ob[(size_t)r * HW_ + c]       = make_float2(o0, o1);
            *(float2*)&ob[(size_t)(r + 8) * HW_ + c] = make_float2(o2, o3);
        }
    }
}

// =====================================================================
extern "C" void kernel_launch(void* const* d_in, const int* in_sizes, int n_in,
                              void* d_out, int out_size) {
    const float* x      = (const float*)d_in[0];
    const float* w_qkv  = (const float*)d_in[1];
    const float* w_out  = (const float*)d_in[2];
    const float* b_out  = (const float*)d_in[3];
    const float* gamma  = (const float*)d_in[4];
    const float* beta   = (const float*)d_in[5];
    float* out = (float*)d_out;

    cudaFuncSetAttribute(k_q_gemm, cudaFuncAttributeMaxDynamicSharedMemorySize,
                         (int)sizeof(GemmBufs));
    cudaFuncSetAttribute(k_kv_ctx, cudaFuncAttributeMaxDynamicSharedMemorySize,
                         (int)sizeof(KvSmem));
    cudaFuncSetAttribute(k_out_ln_tf32, cudaFuncAttributeMaxDynamicSharedMemorySize,
                         (int)sizeof(OutSmem));

    dim3 g1((B_ * HW_) / 128, C_ / 128);          // 512 x 2
    k_q_gemm<<<g1, 256, sizeof(GemmBufs)>>>(x, w_qkv);

    dim3 g2(4, 32, B_);                           // head-pairs x pixel-tiles x batch
    k_kv_ctx<<<g2, 256, sizeof(KvSmem)>>>(x, w_qkv);

    dim3 g3(HEADS_, B_);                          // 8 x 16
    k_weff<<<g3, 256>>>(w_out);

    k_out_ln_tf32<<<(B_ * HW_) / 64, 256, sizeof(OutSmem)>>>(b_out, gamma, beta, out);
}